// round 7
// baseline (speedup 1.0000x reference)
#include <cuda_runtime.h>
#include <math.h>
#include <stdint.h>

// Problem constants
#define D     1024
#define H_    16
#define HD    64
#define FF    4096
#define NB    2
#define LQ    2048
#define MROWS (NB * LQ)   // 4096
#define EPS   1e-5f

// ---------------------------------------------------------------------------
// Scratch (device globals — no allocation allowed)
// ---------------------------------------------------------------------------
__device__ float g_qkv  [MROWS * 3 * D];
__device__ float g_attn [MROWS * D];
__device__ float g_proj [MROWS * D];
__device__ float g_h    [MROWS * D];
__device__ float g_ff1  [MROWS * FF];
__device__ float g_ff2  [MROWS * D];
__device__ float g_wqkvT[3 * D * D];
__device__ float g_woT  [D * D];
__device__ float g_w1T  [FF * D];
__device__ float g_w2T  [D * FF];

__device__ __forceinline__ float* scratch(int id) {
    switch (id) {
        case 0:  return g_qkv;
        case 1:  return g_attn;
        case 2:  return g_proj;
        case 3:  return g_h;
        case 4:  return g_ff1;
        case 5:  return g_ff2;
        case 6:  return g_wqkvT;
        case 7:  return g_woT;
        case 8:  return g_w1T;
        default: return g_w2T;
    }
}

// ---------------------------------------------------------------------------
// tf32 helpers (mma.sync path — base sm_103 target OK)
// ---------------------------------------------------------------------------
__device__ __forceinline__ uint32_t f2tf32(float x) {
    uint32_t r;
    asm("cvt.rna.tf32.f32 %0, %1;" : "=r"(r) : "f"(x));
    return r;
}

__device__ __forceinline__ void mma_tf32(float* c, const uint32_t* a, const uint32_t* b) {
    asm volatile(
        "mma.sync.aligned.m16n8k8.row.col.f32.tf32.tf32.f32 "
        "{%0,%1,%2,%3}, {%4,%5,%6,%7}, {%8,%9}, {%0,%1,%2,%3};"
        : "+f"(c[0]), "+f"(c[1]), "+f"(c[2]), "+f"(c[3])
        : "r"(a[0]), "r"(a[1]), "r"(a[2]), "r"(a[3]),
          "r"(b[0]), "r"(b[1]));
}

// ---------------------------------------------------------------------------
// Weight transpose: dst[c][r] = src[r][c]
// ---------------------------------------------------------------------------
__global__ __launch_bounds__(256)
void transpose_k(const float* __restrict__ src, int dstId, int R, int C)
{
    __shared__ float t[32][33];
    float* dst = scratch(dstId);
    const int bx = blockIdx.x * 32;
    const int by = blockIdx.y * 32;
    const int tx = threadIdx.x & 31;
    const int ty = threadIdx.x >> 5;
    #pragma unroll
    for (int i = 0; i < 32; i += 8)
        t[ty + i][tx] = src[(size_t)(by + ty + i) * C + bx + tx];
    __syncthreads();
    #pragma unroll
    for (int i = 0; i < 32; i += 8)
        dst[(size_t)(bx + ty + i) * R + by + tx] = t[tx][ty + i];
}

// ---------------------------------------------------------------------------
// TF32 tensor-core GEMM: C[M,N] = A[M,K] @ Bt[N,K]^T + bias (opt ReLU)
// Block tile 128x256, warp tile 64x64 (8 warps), BK=16.
// Permuted conflict-free lds.64 layout (stride 24) + register-staged
// double buffering (one __syncthreads per chunk). Dynamic smem 72 KB.
// ---------------------------------------------------------------------------
#define AS_STRIDE 24
#define A_WORDS (128 * AS_STRIDE)          // 3072
#define B_WORDS (256 * AS_STRIDE)          // 6144
#define BUF_WORDS (A_WORDS + B_WORDS)      // 9216
#define GEMM_SMEM (2 * BUF_WORDS * 4)      // 73728 bytes

__global__ __launch_bounds__(256, 1)
void gemm_tf32(const float* __restrict__ Aext, int Aid, int Bid,
               const float* __restrict__ bias,
               float* __restrict__ Cext, int Cid,
               int M, int N, int K, int relu)
{
    extern __shared__ uint32_t dynsm[];

    const float* A  = Aext ? Aext : scratch(Aid);
    const float* Bt = scratch(Bid);
    float*       C  = Cext ? Cext : scratch(Cid);

    const int tid   = threadIdx.x;
    const int wid   = tid >> 5;
    const int lane  = tid & 31;
    const int gid   = lane >> 2;
    const int tig   = lane & 3;
    const int warpM = (wid & 1) * 64;
    const int warpN = (wid >> 1) * 64;
    const int m0    = blockIdx.y * 128;
    const int n0    = blockIdx.x * 256;

    // loader coords
    const int lr    = tid >> 2;                       // 0..63
    const int lc4   = tid & 3;                        // k-group of 4
    const int wbase = (lc4 >> 1) * 8 + (lc4 & 1);

    const float* a_src0 = &A [(size_t)(m0 + lr)       * K + lc4 * 4];
    const float* a_src1 = &A [(size_t)(m0 + lr + 64)  * K + lc4 * 4];
    const float* b_src0 = &Bt[(size_t)(n0 + lr)       * K + lc4 * 4];
    const float* b_src1 = &Bt[(size_t)(n0 + lr + 64)  * K + lc4 * 4];
    const float* b_src2 = &Bt[(size_t)(n0 + lr + 128) * K + lc4 * 4];
    const float* b_src3 = &Bt[(size_t)(n0 + lr + 192) * K + lc4 * 4];

    float acc[4][8][4];
    #pragma unroll
    for (int mt = 0; mt < 4; mt++)
        #pragma unroll
        for (int nt = 0; nt < 8; nt++)
            #pragma unroll
            for (int c = 0; c < 4; c++) acc[mt][nt][c] = 0.f;

    const int nk = K >> 4;

    // prolog: chunk 0 -> buffer 0
    {
        uint32_t* asb = dynsm;
        uint32_t* bsb = dynsm + A_WORDS;
        float4 v;
        v = *(const float4*)a_src0;
        { uint32_t* d = &asb[lr * AS_STRIDE + wbase];
          d[0]=f2tf32(v.x); d[2]=f2tf32(v.y); d[4]=f2tf32(v.z); d[6]=f2tf32(v.w); }
        v = *(const float4*)a_src1;
        { uint32_t* d = &asb[(lr + 64) * AS_STRIDE + wbase];
          d[0]=f2tf32(v.x); d[2]=f2tf32(v.y); d[4]=f2tf32(v.z); d[6]=f2tf32(v.w); }
        v = *(const float4*)b_src0;
        { uint32_t* d = &bsb[lr * AS_STRIDE + wbase];
          d[0]=f2tf32(v.x); d[2]=f2tf32(v.y); d[4]=f2tf32(v.z); d[6]=f2tf32(v.w); }
        v = *(const float4*)b_src1;
        { uint32_t* d = &bsb[(lr + 64) * AS_STRIDE + wbase];
          d[0]=f2tf32(v.x); d[2]=f2tf32(v.y); d[4]=f2tf32(v.z); d[6]=f2tf32(v.w); }
        v = *(const float4*)b_src2;
        { uint32_t* d = &bsb[(lr + 128) * AS_STRIDE + wbase];
          d[0]=f2tf32(v.x); d[2]=f2tf32(v.y); d[4]=f2tf32(v.z); d[6]=f2tf32(v.w); }
        v = *(const float4*)b_src3;
        { uint32_t* d = &bsb[(lr + 192) * AS_STRIDE + wbase];
          d[0]=f2tf32(v.x); d[2]=f2tf32(v.y); d[4]=f2tf32(v.z); d[6]=f2tf32(v.w); }
    }
    __syncthreads();

    for (int kc = 0; kc < nk; kc++) {
        const int buf = kc & 1;

        // prefetch chunk kc+1 into registers
        float4 pa0, pa1, pb0, pb1, pb2, pb3;
        const bool more = (kc + 1 < nk);
        if (more) {
            const int ko = (kc + 1) * 16;
            pa0 = *(const float4*)(a_src0 + ko);
            pa1 = *(const float4*)(a_src1 + ko);
            pb0 = *(const float4*)(b_src0 + ko);
            pb1 = *(const float4*)(b_src1 + ko);
            pb2 = *(const float4*)(b_src2 + ko);
            pb3 = *(const float4*)(b_src3 + ko);
        }

        // compute chunk kc
        const uint32_t* as = dynsm + buf * BUF_WORDS;
        const uint32_t* bs = as + A_WORDS;
        #pragma unroll
        for (int ks = 0; ks < 2; ks++) {
            uint32_t bfr[8][2];
            #pragma unroll
            for (int nt = 0; nt < 8; nt++) {
                uint2 v = *(const uint2*)&bs[(warpN + nt * 8 + gid) * AS_STRIDE + ks * 8 + 2 * tig];
                bfr[nt][0] = v.x;
                bfr[nt][1] = v.y;
            }
            #pragma unroll
            for (int mt = 0; mt < 4; mt++) {
                uint2 lo = *(const uint2*)&as[(warpM + mt * 16 +     gid) * AS_STRIDE + ks * 8 + 2 * tig];
                uint2 hi = *(const uint2*)&as[(warpM + mt * 16 + 8 + gid) * AS_STRIDE + ks * 8 + 2 * tig];
                uint32_t af[4];
                af[0] = lo.x; af[1] = hi.x; af[2] = lo.y; af[3] = hi.y;
                #pragma unroll
                for (int nt = 0; nt < 8; nt++)
                    mma_tf32(acc[mt][nt], af, bfr[nt]);
            }
        }

        // store prefetched chunk to the other buffer
        if (more) {
            uint32_t* asb = dynsm + (buf ^ 1) * BUF_WORDS;
            uint32_t* bsb = asb + A_WORDS;
            { uint32_t* d = &asb[lr * AS_STRIDE + wbase];
              d[0]=f2tf32(pa0.x); d[2]=f2tf32(pa0.y); d[4]=f2tf32(pa0.z); d[6]=f2tf32(pa0.w); }
            { uint32_t* d = &asb[(lr + 64) * AS_STRIDE + wbase];
              d[0]=f2tf32(pa1.x); d[2]=f2tf32(pa1.y); d[4]=f2tf32(pa1.z); d[6]=f2tf32(pa1.w); }
            { uint32_t* d = &bsb[lr * AS_STRIDE + wbase];
              d[0]=f2tf32(pb0.x); d[2]=f2tf32(pb0.y); d[4]=f2tf32(pb0.z); d[6]=f2tf32(pb0.w); }
            { uint32_t* d = &bsb[(lr + 64) * AS_STRIDE + wbase];
              d[0]=f2tf32(pb1.x); d[2]=f2tf32(pb1.y); d[4]=f2tf32(pb1.z); d[6]=f2tf32(pb1.w); }
            { uint32_t* d = &bsb[(lr + 128) * AS_STRIDE + wbase];
              d[0]=f2tf32(pb2.x); d[2]=f2tf32(pb2.y); d[4]=f2tf32(pb2.z); d[6]=f2tf32(pb2.w); }
            { uint32_t* d = &bsb[(lr + 192) * AS_STRIDE + wbase];
              d[0]=f2tf32(pb3.x); d[2]=f2tf32(pb3.y); d[4]=f2tf32(pb3.z); d[6]=f2tf32(pb3.w); }
            __syncthreads();
        }
    }

    #pragma unroll
    for (int nt = 0; nt < 8; nt++) {
        const int n = n0 + warpN + nt * 8 + 2 * tig;
        const float b0 = bias[n], b1 = bias[n + 1];
        #pragma unroll
        for (int mt = 0; mt < 4; mt++) {
            const int m = m0 + warpM + mt * 16 + gid;
            float2 v0 = make_float2(acc[mt][nt][0] + b0, acc[mt][nt][1] + b1);
            float2 v1 = make_float2(acc[mt][nt][2] + b0, acc[mt][nt][3] + b1);
            if (relu) {
                v0.x = fmaxf(v0.x, 0.f); v0.y = fmaxf(v0.y, 0.f);
                v1.x = fmaxf(v1.x, 0.f); v1.y = fmaxf(v1.y, 0.f);
            }
            *(float2*)&C[(size_t)m * N + n]       = v0;
            *(float2*)&C[(size_t)(m + 8) * N + n] = v1;
        }
    }
}

// ---------------------------------------------------------------------------
// Tensor-core flash attention (tf32 mma.sync) — unchanged
// ---------------------------------------------------------------------------
#define KS_STRIDE 72
#define VS_STRIDE 74

__global__ __launch_bounds__(128)
void attn_mma()
{
    __shared__ uint32_t sm[64 * KS_STRIDE + 64 * VS_STRIDE];

    const int nB  = blockIdx.z;
    const int h   = blockIdx.y;
    const int q0  = blockIdx.x * 128;
    const int tid = threadIdx.x;
    const int wid = tid >> 5;
    const int lane = tid & 31;
    const int gid  = lane >> 2;
    const int tig  = lane & 3;
    const int warpM = wid * 32;
    const float qscale = 0.125f * 1.44269504f;

    #pragma unroll
    for (int t = 0; t < 16; t++) {
        const int i  = tid + t * 128;
        const int r  = i >> 4;
        const int c4 = i & 15;
        const float4 v = *(const float4*)&g_qkv[(size_t)(nB * LQ + q0 + r) * (3 * D) + h * HD + c4 * 4];
        uint32_t* dst = &sm[r * KS_STRIDE + (c4 >> 2) * 16 + ((c4 & 3) >> 1) * 8 + (c4 & 1)];
        dst[0] = f2tf32(v.x * qscale); dst[2] = f2tf32(v.y * qscale);
        dst[4] = f2tf32(v.z * qscale); dst[6] = f2tf32(v.w * qscale);
    }
    __syncthreads();

    uint32_t qf[2][8][4];
    #pragma unroll
    for (int mt = 0; mt < 2; mt++) {
        const int rlo = warpM + mt * 16 + gid;
        #pragma unroll
        for (int ks = 0; ks < 8; ks++) {
            uint2 lo = *(const uint2*)&sm[ rlo      * KS_STRIDE + (ks >> 1) * 16 + (ks & 1) * 8 + 2 * tig];
            uint2 hi = *(const uint2*)&sm[(rlo + 8) * KS_STRIDE + (ks >> 1) * 16 + (ks & 1) * 8 + 2 * tig];
            qf[mt][ks][0] = lo.x; qf[mt][ks][1] = hi.x;
            qf[mt][ks][2] = lo.y; qf[mt][ks][3] = hi.y;
        }
    }
    __syncthreads();

    uint32_t* Ks = sm;
    uint32_t* Vs = sm + 64 * KS_STRIDE;

    float oac[2][8][4];
    #pragma unroll
    for (int mt = 0; mt < 2; mt++)
        #pragma unroll
        for (int nt = 0; nt < 8; nt++)
            #pragma unroll
            for (int c = 0; c < 4; c++) oac[mt][nt][c] = 0.f;
    float mrow[2][2] = {{-1e30f, -1e30f}, {-1e30f, -1e30f}};
    float lrow[2][2] = {{0.f, 0.f}, {0.f, 0.f}};

    for (int kt = 0; kt < LQ / 64; kt++) {
        #pragma unroll
        for (int t = 0; t < 8; t++) {
            const int i  = tid + t * 128;
            const int r  = i >> 4;
            const int c4 = i & 15;
            const size_t base = (size_t)(nB * LQ + kt * 64 + r) * (3 * D) + h * HD + c4 * 4;
            const float4 v = *(const float4*)&g_qkv[base + D];
            uint32_t* dst = &Ks[r * KS_STRIDE + (c4 >> 2) * 16 + ((c4 & 3) >> 1) * 8 + (c4 & 1)];
            dst[0] = f2tf32(v.x); dst[2] = f2tf32(v.y);
            dst[4] = f2tf32(v.z); dst[6] = f2tf32(v.w);
        }
        #pragma unroll
        for (int t = 0; t < 8; t++) {
            const int i   = tid + t * 128;
            const int key = i >> 4;
            const int c4  = i & 15;
            const size_t base = (size_t)(nB * LQ + kt * 64 + key) * (3 * D) + h * HD + c4 * 4;
            const float4 v = *(const float4*)&g_qkv[base + 2 * D];
            const int kpos = (key >> 4) * 16 + ((key & 3) << 1) + ((key >> 2) & 1) + (key & 8);
            const int d0 = c4 * 4;
            Vs[(d0 + 0) * VS_STRIDE + kpos] = f2tf32(v.x);
            Vs[(d0 + 1) * VS_STRIDE + kpos] = f2tf32(v.y);
            Vs[(d0 + 2) * VS_STRIDE + kpos] = f2tf32(v.z);
            Vs[(d0 + 3) * VS_STRIDE + kpos] = f2tf32(v.w);
        }
        __syncthreads();

        float sacc[2][8][4];
        #pragma unroll
        for (int mt = 0; mt < 2; mt++)
            #pragma unroll
            for (int nt = 0; nt < 8; nt++)
                #pragma unroll
                for (int c = 0; c < 4; c++) sacc[mt][nt][c] = 0.f;

        #pragma unroll
        for (int ks = 0; ks < 8; ks++) {
            #pragma unroll
            for (int nt = 0; nt < 8; nt++) {
                uint2 bv = *(const uint2*)&Ks[(nt * 8 + gid) * KS_STRIDE + (ks >> 1) * 16 + (ks & 1) * 8 + 2 * tig];
                uint32_t bf[2] = {bv.x, bv.y};
                mma_tf32(sacc[0][nt], qf[0][ks], bf);
                mma_tf32(sacc[1][nt], qf[1][ks], bf);
            }
        }

        #pragma unroll
        for (int mt = 0; mt < 2; mt++) {
            float mx0 = -1e30f, mx1 = -1e30f;
            #pragma unroll
            for (int nt = 0; nt < 8; nt++) {
                mx0 = fmaxf(mx0, fmaxf(sacc[mt][nt][0], sacc[mt][nt][1]));
                mx1 = fmaxf(mx1, fmaxf(sacc[mt][nt][2], sacc[mt][nt][3]));
            }
            mx0 = fmaxf(mx0, __shfl_xor_sync(0xFFFFFFFFu, mx0, 1));
            mx0 = fmaxf(mx0, __shfl_xor_sync(0xFFFFFFFFu, mx0, 2));
            mx1 = fmaxf(mx1, __shfl_xor_sync(0xFFFFFFFFu, mx1, 1));
            mx1 = fmaxf(mx1, __shfl_xor_sync(0xFFFFFFFFu, mx1, 2));

            const float mn0 = fmaxf(mrow[mt][0], mx0);
            const float mn1 = fmaxf(mrow[mt][1], mx1);
            const float cr0 = exp2f(mrow[mt][0] - mn0);
            const float cr1 = exp2f(mrow[mt][1] - mn1);
            mrow[mt][0] = mn0;
            mrow[mt][1] = mn1;

            float ls0 = 0.f, ls1 = 0.f;
            #pragma unroll
            for (int nt = 0; nt < 8; nt++) {
                sacc[mt][nt][0] = exp2f(sacc[mt][nt][0] - mn0);
                sacc[mt][nt][1] = exp2f(sacc[mt][nt][1] - mn0);
                sacc[mt][nt][2] = exp2f(sacc[mt][nt][2] - mn1);
                sacc[mt][nt][3] = exp2f(sacc[mt][nt][3] - mn1);
                ls0 += sacc[mt][nt][0] + sacc[mt][nt][1];
                ls1 += sacc[mt][nt][2] + sacc[mt][nt][3];
            }
            ls0 += __shfl_xor_sync(0xFFFFFFFFu, ls0, 1);
            ls0 += __shfl_xor_sync(0xFFFFFFFFu, ls0, 2);
            ls1 += __shfl_xor_sync(0xFFFFFFFFu, ls1, 1);
            ls1 += __shfl_xor_sync(0xFFFFFFFFu, ls1, 2);
            lrow[mt][0] = lrow[mt][0] * cr0 + ls0;
            lrow[mt][1] = lrow[mt][1] * cr1 + ls1;

            #pragma unroll
            for (int nt = 0; nt < 8; nt++) {
                oac[mt][nt][0] *= cr0; oac[mt][nt][1] *= cr0;
                oac[mt][nt][2] *= cr1; oac[mt][nt][3] *= cr1;
            }
        }

        const int s1 = (lane & ~3) | (tig >> 1);
        const int s2 = s1 + 2;
        const bool odd = (tig & 1) != 0;
        #pragma unroll
        for (int kk = 0; kk < 8; kk++) {
            uint32_t pa[2][4];
            #pragma unroll
            for (int mt = 0; mt < 2; mt++) {
                const float c0 = sacc[mt][kk][0], c1 = sacc[mt][kk][1];
                const float c2 = sacc[mt][kk][2], c3 = sacc[mt][kk][3];
                const float x0 = __shfl_sync(0xFFFFFFFFu, c0, s1);
                const float x1 = __shfl_sync(0xFFFFFFFFu, c1, s1);
                const float x2 = __shfl_sync(0xFFFFFFFFu, c2, s1);
                const float x3 = __shfl_sync(0xFFFFFFFFu, c3, s1);
                const float y0 = __shfl_sync(0xFFFFFFFFu, c0, s2);
                const float y1 = __shfl_sync(0xFFFFFFFFu, c1, s2);
                const float y2 = __shfl_sync(0xFFFFFFFFu, c2, s2);
                const float y3 = __shfl_sync(0xFFFFFFFFu, c3, s2);
                pa[mt][0] = f2tf32(odd ? x1 : x0);
                pa[mt][1] = f2tf32(odd ? x3 : x2);
                pa[mt][2] = f2tf32(odd ? y1 : y0);
                pa[mt][3] = f2tf32(odd ? y3 : y2);
            }
            #pragma unroll
            for (int ntd = 0; ntd < 8; ntd++) {
                uint2 bv = *(const uint2*)&Vs[(ntd * 8 + gid) * VS_STRIDE + (kk >> 1) * 16 + (kk & 1) * 8 + 2 * tig];
                uint32_t bf[2] = {bv.x, bv.y};
                mma_tf32(oac[0][ntd], pa[0], bf);
                mma_tf32(oac[1][ntd], pa[1], bf);
            }
        }
        __syncthreads();
    }

    #pragma unroll
    for (int mt = 0; mt < 2; mt++) {
        const float inv0 = 1.f / lrow[mt][0];
        const float inv1 = 1.f / lrow[mt][1];
        const int grow = nB * LQ + q0 + warpM + mt * 16 + gid;
        #pragma unroll
        for (int ntd = 0; ntd < 8; ntd++) {
            const int col = h * HD + ntd * 8 + 2 * tig;
            *(float2*)&g_attn[(size_t)grow * D + col] =
                make_float2(oac[mt][ntd][0] * inv0, oac[mt][ntd][1] * inv0);
            *(float2*)&g_attn[(size_t)(grow + 8) * D + col] =
                make_float2(oac[mt][ntd][2] * inv1, oac[mt][ntd][3] * inv1);
        }
    }
}

// ---------------------------------------------------------------------------
// Residual add + LayerNorm
// ---------------------------------------------------------------------------
__global__ __launch_bounds__(256)
void add_ln_kernel(const float* __restrict__ aext, int aid,
                   const float* __restrict__ bext, int bid,
                   const float* __restrict__ gamma,
                   const float* __restrict__ beta,
                   float* __restrict__ outext, int outid)
{
    const float* a = aext ? aext : scratch(aid);
    const float* b = bext ? bext : scratch(bid);
    float*       o = outext ? outext : scratch(outid);

    const int row = blockIdx.x;
    const int tid = threadIdx.x;
    const size_t base = (size_t)row * D;

    float v[4];
    float s = 0.f, s2 = 0.f;
    #pragma unroll
    for (int i = 0; i < 4; i++) {
        int col = tid + i * 256;
        float x = a[base + col] + b[base + col];
        v[i] = x;
        s  += x;
        s2 += x * x;
    }
    #pragma unroll
    for (int off = 16; off; off >>= 1) {
        s  += __shfl_xor_sync(0xFFFFFFFFu, s,  off);
        s2 += __shfl_xor_sync(0xFFFFFFFFu, s2, off);
    }
    __shared__ float rs[8], rs2[8];
    const int warp = tid >> 5, lane = tid & 31;
    if (lane == 0) { rs[warp] = s; rs2[warp] = s2; }
    __syncthreads();
    float ts = 0.f, ts2 = 0.f;
    #pragma unroll
    for (int w = 0; w < 8; w++) { ts += rs[w]; ts2 += rs2[w]; }

    const float mu  = ts * (1.f / D);
    const float var = ts2 * (1.f / D) - mu * mu;
    const float inv = rsqrtf(var + EPS);

    #pragma unroll
    for (int i = 0; i < 4; i++) {
        int col = tid + i * 256;
        o[base + col] = (v[i] - mu) * inv * gamma[col] + beta[col];
    }
}

// ---------------------------------------------------------------------------
// Launch
// ---------------------------------------------------------------------------
extern "C" void kernel_launch(void* const* d_in, const int* in_sizes, int n_in,
                              void* d_out, int out_size)
{
    const float* x     = (const float*)d_in[0];
    const float* w_qkv = (const float*)d_in[1];
    const float* b_qkv = (const float*)d_in[2];
    const float* w_o   = (const float*)d_in[3];
    const float* b_o   = (const float*)d_in[4];
    const float* g1    = (const float*)d_in[5];
    const float* be1   = (const float*)d_in[6];
    const float* w1    = (const float*)d_in[7];
    const float* b1    = (const float*)d_in[8];
    const float* w2    = (const float*)d_in[9];
    const float* b2    = (const float*)d_in[10];
    const float* g2    = (const float*)d_in[11];
    const float* be2   = (const float*)d_in[12];
    float* out = (float*)d_out;

    cudaFuncSetAttribute(gemm_tf32,
                         cudaFuncAttributeMaxDynamicSharedMemorySize, GEMM_SMEM);

    // Transpose weights -> [N,K] K-major operands
    transpose_k<<<dim3(3 * D / 32, D / 32), 256>>>(w_qkv, 6, D, 3 * D);
    transpose_k<<<dim3(D / 32,     D / 32), 256>>>(w_o,   7, D, D);
    transpose_k<<<dim3(FF / 32,    D / 32), 256>>>(w1,    8, D, FF);
    transpose_k<<<dim3(D / 32,    FF / 32), 256>>>(w2,    9, FF, D);

    // 1. QKV
    gemm_tf32<<<dim3(3 * D / 256, MROWS / 128), 256, GEMM_SMEM>>>(
        x, -1, 6, b_qkv, nullptr, 0, MROWS, 3 * D, D, 0);

    // 2. attention (tensor-core flash)
    attn_mma<<<dim3(LQ / 128, H_, NB), 128>>>();

    // 3. proj
    gemm_tf32<<<dim3(D / 256, MROWS / 128), 256, GEMM_SMEM>>>(
        nullptr, 1, 7, b_o, nullptr, 2, MROWS, D, D, 0);

    // 4. h = LN(proj + x)
    add_ln_kernel<<<MROWS, 256>>>(nullptr, 2, x, -1, g1, be1, nullptr, 3);

    // 5. FF1 (+ReLU)
    gemm_tf32<<<dim3(FF / 256, MROWS / 128), 256, GEMM_SMEM>>>(
        nullptr, 3, 8, b1, nullptr, 4, MROWS, FF, D, 1);

    // 6. FF2
    gemm_tf32<<<dim3(D / 256, MROWS / 128), 256, GEMM_SMEM>>>(
        nullptr, 4, 9, b2, nullptr, 5, MROWS, D, FF, 0);

    // 7. out = LN(h + ff2)
    add_ln_kernel<<<MROWS, 256>>>(nullptr, 3, nullptr, 5, g2, be2, out, -1);
}

// round 8
// speedup vs baseline: 1.2208x; 1.2208x over previous
#include <cuda_runtime.h>
#include <cuda_fp16.h>
#include <math.h>
#include <stdint.h>

// Problem constants
#define D     1024
#define H_    16
#define HD    64
#define FF    4096
#define NB    2
#define LQ    2048
#define MROWS (NB * LQ)   // 4096
#define EPS   1e-5f

// ---------------------------------------------------------------------------
// Scratch (device globals — no allocation allowed)
// ---------------------------------------------------------------------------
__device__ float g_qkv  [MROWS * 3 * D];
__device__ float g_attn [MROWS * D];
__device__ float g_proj [MROWS * D];
__device__ float g_h    [MROWS * D];
__device__ float g_ff1  [MROWS * FF];
__device__ float g_ff2  [MROWS * D];
__device__ float g_wqkvT[3 * D * D];
__device__ float g_woT  [D * D];
__device__ float g_w1T  [FF * D];
__device__ float g_w2T  [D * FF];

__device__ __forceinline__ float* scratch(int id) {
    switch (id) {
        case 0:  return g_qkv;
        case 1:  return g_attn;
        case 2:  return g_proj;
        case 3:  return g_h;
        case 4:  return g_ff1;
        case 5:  return g_ff2;
        case 6:  return g_wqkvT;
        case 7:  return g_woT;
        case 8:  return g_w1T;
        default: return g_w2T;
    }
}

// ---------------------------------------------------------------------------
// mma helpers (base sm_103 target OK)
// ---------------------------------------------------------------------------
__device__ __forceinline__ uint32_t f2tf32(float x) {
    uint32_t r;
    asm("cvt.rna.tf32.f32 %0, %1;" : "=r"(r) : "f"(x));
    return r;
}

__device__ __forceinline__ void mma_tf32(float* c, const uint32_t* a, const uint32_t* b) {
    asm volatile(
        "mma.sync.aligned.m16n8k8.row.col.f32.tf32.tf32.f32 "
        "{%0,%1,%2,%3}, {%4,%5,%6,%7}, {%8,%9}, {%0,%1,%2,%3};"
        : "+f"(c[0]), "+f"(c[1]), "+f"(c[2]), "+f"(c[3])
        : "r"(a[0]), "r"(a[1]), "r"(a[2]), "r"(a[3]),
          "r"(b[0]), "r"(b[1]));
}

__device__ __forceinline__ void mma_f16(float* c, const uint32_t* a, const uint32_t* b) {
    asm volatile(
        "mma.sync.aligned.m16n8k16.row.col.f32.f16.f16.f32 "
        "{%0,%1,%2,%3}, {%4,%5,%6,%7}, {%8,%9}, {%0,%1,%2,%3};"
        : "+f"(c[0]), "+f"(c[1]), "+f"(c[2]), "+f"(c[3])
        : "r"(a[0]), "r"(a[1]), "r"(a[2]), "r"(a[3]),
          "r"(b[0]), "r"(b[1]));
}

__device__ __forceinline__ uint32_t packh2(float a, float b) {
    __half2 h = __floats2half2_rn(a, b);   // low = a (smaller k)
    return *(uint32_t*)&h;
}

// ---------------------------------------------------------------------------
// Weight transpose: dst[c][r] = src[r][c]
// ---------------------------------------------------------------------------
__global__ __launch_bounds__(256)
void transpose_k(const float* __restrict__ src, int dstId, int R, int C)
{
    __shared__ float t[32][33];
    float* dst = scratch(dstId);
    const int bx = blockIdx.x * 32;
    const int by = blockIdx.y * 32;
    const int tx = threadIdx.x & 31;
    const int ty = threadIdx.x >> 5;
    #pragma unroll
    for (int i = 0; i < 32; i += 8)
        t[ty + i][tx] = src[(size_t)(by + ty + i) * C + bx + tx];
    __syncthreads();
    #pragma unroll
    for (int i = 0; i < 32; i += 8)
        dst[(size_t)(bx + ty + i) * R + by + tx] = t[tx][ty + i];
}

// ---------------------------------------------------------------------------
// FP16 tensor-core GEMM: C[M,N] = A[M,K] @ Bt[N,K]^T + bias (opt ReLU)
// Block 128x128, 8 warps (64x32 warp tile), BK=32 (2 k16 planes / chunk).
// Plane layout: 128 rows x 8 words, stride 8, pair-permuted
// [p0,p4,p1,p5,p2,p6,p3,p7] -> conflict-free lds.64 frags + STS.32 stores.
// Register-staged double buffering, one __syncthreads per BK=32 chunk.
// fp16 mantissa == tf32 mantissa (10 bits): precision preserved.
// ---------------------------------------------------------------------------
#define APLANE 1026                 // words between plane bases (+2 bank shift)
#define AB_OFF 2052                 // B region offset inside buffer
#define BUFW   4104                 // words per chunk buffer

__global__ __launch_bounds__(256)
void gemm_f16(const float* __restrict__ Aext, int Aid, int Bid,
              const float* __restrict__ bias,
              float* __restrict__ Cext, int Cid,
              int M, int N, int K, int relu)
{
    __shared__ uint32_t sm[2 * BUFW];   // 32.8 KB

    const float* A  = Aext ? Aext : scratch(Aid);
    const float* Bt = scratch(Bid);
    float*       C  = Cext ? Cext : scratch(Cid);

    const int tid   = threadIdx.x;
    const int wid   = tid >> 5;
    const int lane  = tid & 31;
    const int gid   = lane >> 2;
    const int tig   = lane & 3;
    const int warpM = (wid & 1) * 64;
    const int warpN = (wid >> 1) * 32;
    const int m0    = blockIdx.y * 128;
    const int n0    = blockIdx.x * 128;

    // loader coords: thread -> (row lr + 32i, float4 group c4 of 8)
    const int lr  = tid >> 3;          // 0..31
    const int c4  = tid & 7;           // 0..7
    const int spl = c4 >> 2;           // plane 0/1
    const int cc  = c4 & 3;            // float4 within plane (k = 4*cc..+3)
    const int p0  = (cc < 2) ? 4 * cc     : 4 * cc - 7;  // pos of pair 2cc
    const int p1  = (cc < 2) ? 4 * cc + 2 : 4 * cc - 5;  // pos of pair 2cc+1
    const int sb0 = spl * APLANE + lr * 8;               // word base (A side)

    const float* aS[4];
    const float* bS[4];
    #pragma unroll
    for (int i = 0; i < 4; i++) {
        aS[i] = &A [(size_t)(m0 + lr + 32 * i) * K + c4 * 4];
        bS[i] = &Bt[(size_t)(n0 + lr + 32 * i) * K + c4 * 4];
    }

    float acc[4][4][4];
    #pragma unroll
    for (int mt = 0; mt < 4; mt++)
        #pragma unroll
        for (int nt = 0; nt < 4; nt++)
            #pragma unroll
            for (int c = 0; c < 4; c++) acc[mt][nt][c] = 0.f;

    const int nk = K >> 5;   // BK=32 chunks

    // prolog: chunk 0 -> buffer 0
    {
        uint32_t* dst = sm;
        #pragma unroll
        for (int i = 0; i < 4; i++) {
            const float4 va = *(const float4*)aS[i];
            const float4 vb = *(const float4*)bS[i];
            const int rb = sb0 + i * 256;    // 32 rows * 8 words
            dst[rb + p0]          = packh2(va.x, va.y);
            dst[rb + p1]          = packh2(va.z, va.w);
            dst[AB_OFF + rb + p0] = packh2(vb.x, vb.y);
            dst[AB_OFF + rb + p1] = packh2(vb.z, vb.w);
        }
    }
    __syncthreads();

    for (int kc = 0; kc < nk; kc++) {
        const int buf = kc & 1;

        // prefetch chunk kc+1 (raw fp32) into registers
        float4 va[4], vb[4];
        const bool more = (kc + 1 < nk);
        if (more) {
            const int ko = (kc + 1) * 32;
            #pragma unroll
            for (int i = 0; i < 4; i++) {
                va[i] = *(const float4*)(aS[i] + ko);
                vb[i] = *(const float4*)(bS[i] + ko);
            }
        }

        // compute chunk kc: 2 planes of k16
        const uint32_t* as = sm + buf * BUFW;
        const uint32_t* bs = as + AB_OFF;
        #pragma unroll
        for (int ks = 0; ks < 2; ks++) {
            const uint32_t* ap = as + ks * APLANE;
            const uint32_t* bp = bs + ks * APLANE;
            uint32_t bfr[4][2];
            #pragma unroll
            for (int nt = 0; nt < 4; nt++) {
                uint2 v = *(const uint2*)&bp[(warpN + nt * 8 + gid) * 8 + 2 * tig];
                bfr[nt][0] = v.x;    // pairs (2tig,2tig+1)
                bfr[nt][1] = v.y;    // pairs (2tig+8,2tig+9)
            }
            #pragma unroll
            for (int mt = 0; mt < 4; mt++) {
                uint2 lo = *(const uint2*)&ap[(warpM + mt * 16 +     gid) * 8 + 2 * tig];
                uint2 hi = *(const uint2*)&ap[(warpM + mt * 16 + 8 + gid) * 8 + 2 * tig];
                uint32_t af[4];
                af[0] = lo.x;   // (row gid,   k 2tig..)
                af[1] = hi.x;   // (row gid+8, k 2tig..)
                af[2] = lo.y;   // (row gid,   k 2tig+8..)
                af[3] = hi.y;   // (row gid+8, k 2tig+8..)
                #pragma unroll
                for (int nt = 0; nt < 4; nt++)
                    mma_f16(acc[mt][nt], af, bfr[nt]);
            }
        }

        // convert + store prefetched chunk to the other buffer
        if (more) {
            uint32_t* dst = sm + (buf ^ 1) * BUFW;
            #pragma unroll
            for (int i = 0; i < 4; i++) {
                const int rb = sb0 + i * 256;
                dst[rb + p0]          = packh2(va[i].x, va[i].y);
                dst[rb + p1]          = packh2(va[i].z, va[i].w);
                dst[AB_OFF + rb + p0] = packh2(vb[i].x, vb[i].y);
                dst[AB_OFF + rb + p1] = packh2(vb[i].z, vb[i].w);
            }
            __syncthreads();
        }
    }

    // epilogue: C frag layout identical to tf32 variant
    #pragma unroll
    for (int nt = 0; nt < 4; nt++) {
        const int n = n0 + warpN + nt * 8 + 2 * tig;
        const float b0 = bias[n], b1 = bias[n + 1];
        #pragma unroll
        for (int mt = 0; mt < 4; mt++) {
            const int m = m0 + warpM + mt * 16 + gid;
            float2 v0 = make_float2(acc[mt][nt][0] + b0, acc[mt][nt][1] + b1);
            float2 v1 = make_float2(acc[mt][nt][2] + b0, acc[mt][nt][3] + b1);
            if (relu) {
                v0.x = fmaxf(v0.x, 0.f); v0.y = fmaxf(v0.y, 0.f);
                v1.x = fmaxf(v1.x, 0.f); v1.y = fmaxf(v1.y, 0.f);
            }
            *(float2*)&C[(size_t)m * N + n]       = v0;
            *(float2*)&C[(size_t)(m + 8) * N + n] = v1;
        }
    }
}

// ---------------------------------------------------------------------------
// Tensor-core flash attention (tf32 mma.sync) — unchanged (R4-validated)
// ---------------------------------------------------------------------------
#define KS_STRIDE 72
#define VS_STRIDE 74

__global__ __launch_bounds__(128)
void attn_mma()
{
    __shared__ uint32_t sm[64 * KS_STRIDE + 64 * VS_STRIDE];

    const int nB  = blockIdx.z;
    const int h   = blockIdx.y;
    const int q0  = blockIdx.x * 128;
    const int tid = threadIdx.x;
    const int wid = tid >> 5;
    const int lane = tid & 31;
    const int gid  = lane >> 2;
    const int tig  = lane & 3;
    const int warpM = wid * 32;
    const float qscale = 0.125f * 1.44269504f;

    #pragma unroll
    for (int t = 0; t < 16; t++) {
        const int i  = tid + t * 128;
        const int r  = i >> 4;
        const int c4 = i & 15;
        const float4 v = *(const float4*)&g_qkv[(size_t)(nB * LQ + q0 + r) * (3 * D) + h * HD + c4 * 4];
        uint32_t* dst = &sm[r * KS_STRIDE + (c4 >> 2) * 16 + ((c4 & 3) >> 1) * 8 + (c4 & 1)];
        dst[0] = f2tf32(v.x * qscale); dst[2] = f2tf32(v.y * qscale);
        dst[4] = f2tf32(v.z * qscale); dst[6] = f2tf32(v.w * qscale);
    }
    __syncthreads();

    uint32_t qf[2][8][4];
    #pragma unroll
    for (int mt = 0; mt < 2; mt++) {
        const int rlo = warpM + mt * 16 + gid;
        #pragma unroll
        for (int ks = 0; ks < 8; ks++) {
            uint2 lo = *(const uint2*)&sm[ rlo      * KS_STRIDE + (ks >> 1) * 16 + (ks & 1) * 8 + 2 * tig];
            uint2 hi = *(const uint2*)&sm[(rlo + 8) * KS_STRIDE + (ks >> 1) * 16 + (ks & 1) * 8 + 2 * tig];
            qf[mt][ks][0] = lo.x; qf[mt][ks][1] = hi.x;
            qf[mt][ks][2] = lo.y; qf[mt][ks][3] = hi.y;
        }
    }
    __syncthreads();

    uint32_t* Ks = sm;
    uint32_t* Vs = sm + 64 * KS_STRIDE;

    float oac[2][8][4];
    #pragma unroll
    for (int mt = 0; mt < 2; mt++)
        #pragma unroll
        for (int nt = 0; nt < 8; nt++)
            #pragma unroll
            for (int c = 0; c < 4; c++) oac[mt][nt][c] = 0.f;
    float mrow[2][2] = {{-1e30f, -1e30f}, {-1e30f, -1e30f}};
    float lrow[2][2] = {{0.f, 0.f}, {0.f, 0.f}};

    for (int kt = 0; kt < LQ / 64; kt++) {
        #pragma unroll
        for (int t = 0; t < 8; t++) {
            const int i  = tid + t * 128;
            const int r  = i >> 4;
            const int c4 = i & 15;
            const size_t base = (size_t)(nB * LQ + kt * 64 + r) * (3 * D) + h * HD + c4 * 4;
            const float4 v = *(const float4*)&g_qkv[base + D];
            uint32_t* dst = &Ks[r * KS_STRIDE + (c4 >> 2) * 16 + ((c4 & 3) >> 1) * 8 + (c4 & 1)];
            dst[0] = f2tf32(v.x); dst[2] = f2tf32(v.y);
            dst[4] = f2tf32(v.z); dst[6] = f2tf32(v.w);
        }
        #pragma unroll
        for (int t = 0; t < 8; t++) {
            const int i   = tid + t * 128;
            const int key = i >> 4;
            const int c4  = i & 15;
            const size_t base = (size_t)(nB * LQ + kt * 64 + key) * (3 * D) + h * HD + c4 * 4;
            const float4 v = *(const float4*)&g_qkv[base + 2 * D];
            const int kpos = (key >> 4) * 16 + ((key & 3) << 1) + ((key >> 2) & 1) + (key & 8);
            const int d0 = c4 * 4;
            Vs[(d0 + 0) * VS_STRIDE + kpos] = f2tf32(v.x);
            Vs[(d0 + 1) * VS_STRIDE + kpos] = f2tf32(v.y);
            Vs[(d0 + 2) * VS_STRIDE + kpos] = f2tf32(v.z);
            Vs[(d0 + 3) * VS_STRIDE + kpos] = f2tf32(v.w);
        }
        __syncthreads();

        float sacc[2][8][4];
        #pragma unroll
        for (int mt = 0; mt < 2; mt++)
            #pragma unroll
            for (int nt = 0; nt < 8; nt++)
                #pragma unroll
                for (int c = 0; c < 4; c++) sacc[mt][nt][c] = 0.f;

        #pragma unroll
        for (int ks = 0; ks < 8; ks++) {
            #pragma unroll
            for (int nt = 0; nt < 8; nt++) {
                uint2 bv = *(const uint2*)&Ks[(nt * 8 + gid) * KS_STRIDE + (ks >> 1) * 16 + (ks & 1) * 8 + 2 * tig];
                uint32_t bf[2] = {bv.x, bv.y};
                mma_tf32(sacc[0][nt], qf[0][ks], bf);
                mma_tf32(sacc[1][nt], qf[1][ks], bf);
            }
        }

        #pragma unroll
        for (int mt = 0; mt < 2; mt++) {
            float mx0 = -1e30f, mx1 = -1e30f;
            #pragma unroll
            for (int nt = 0; nt < 8; nt++) {
                mx0 = fmaxf(mx0, fmaxf(sacc[mt][nt][0], sacc[mt][nt][1]));
                mx1 = fmaxf(mx1, fmaxf(sacc[mt][nt][2], sacc[mt][nt][3]));
            }
            mx0 = fmaxf(mx0, __shfl_xor_sync(0xFFFFFFFFu, mx0, 1));
            mx0 = fmaxf(mx0, __shfl_xor_sync(0xFFFFFFFFu, mx0, 2));
            mx1 = fmaxf(mx1, __shfl_xor_sync(0xFFFFFFFFu, mx1, 1));
            mx1 = fmaxf(mx1, __shfl_xor_sync(0xFFFFFFFFu, mx1, 2));

            const float mn0 = fmaxf(mrow[mt][0], mx0);
            const float mn1 = fmaxf(mrow[mt][1], mx1);
            const float cr0 = exp2f(mrow[mt][0] - mn0);
            const float cr1 = exp2f(mrow[mt][1] - mn1);
            mrow[mt][0] = mn0;
            mrow[mt][1] = mn1;

            float ls0 = 0.f, ls1 = 0.f;
            #pragma unroll
            for (int nt = 0; nt < 8; nt++) {
                sacc[mt][nt][0] = exp2f(sacc[mt][nt][0] - mn0);
                sacc[mt][nt][1] = exp2f(sacc[mt][nt][1] - mn0);
                sacc[mt][nt][2] = exp2f(sacc[mt][nt][2] - mn1);
                sacc[mt][nt][3] = exp2f(sacc[mt][nt][3] - mn1);
                ls0 += sacc[mt][nt][0] + sacc[mt][nt][1];
                ls1 += sacc[mt][nt][2] + sacc[mt][nt][3];
            }
            ls0 += __shfl_xor_sync(0xFFFFFFFFu, ls0, 1);
            ls0 += __shfl_xor_sync(0xFFFFFFFFu, ls0, 2);
            ls1 += __shfl_xor_sync(0xFFFFFFFFu, ls1, 1);
            ls1 += __shfl_xor_sync(0xFFFFFFFFu, ls1, 2);
            lrow[mt][0] = lrow[mt][0] * cr0 + ls0;
            lrow[mt][1] = lrow[mt][1] * cr1 + ls1;

            #pragma unroll
            for (int nt = 0; nt < 8; nt++) {
                oac[mt][nt][0] *= cr0; oac[mt][nt][1] *= cr0;
                oac[mt][nt][2] *= cr1; oac[mt][nt][3] *= cr1;
            }
        }

        const int s1 = (lane & ~3) | (tig >> 1);
        const int s2 = s1 + 2;
        const bool odd = (tig & 1) != 0;
        #pragma unroll
        for (int kk = 0; kk < 8; kk++) {
            uint32_t pa[2][4];
            #pragma unroll
            for (int mt = 0; mt < 2; mt++) {
                const float c0 = sacc[mt][kk][0], c1 = sacc[mt][kk][1];
                const float c2 = sacc[mt][kk][2], c3 = sacc[mt][kk][3];
                const float x0 = __shfl_sync(0xFFFFFFFFu, c0, s1);
                const float x1 = __shfl_sync(0xFFFFFFFFu, c1, s1);
                const float x2 = __shfl_sync(0xFFFFFFFFu, c2, s1);
                const float x3 = __shfl_sync(0xFFFFFFFFu, c3, s1);
                const float y0 = __shfl_sync(0xFFFFFFFFu, c0, s2);
                const float y1 = __shfl_sync(0xFFFFFFFFu, c1, s2);
                const float y2 = __shfl_sync(0xFFFFFFFFu, c2, s2);
                const float y3 = __shfl_sync(0xFFFFFFFFu, c3, s2);
                pa[mt][0] = f2tf32(odd ? x1 : x0);
                pa[mt][1] = f2tf32(odd ? x3 : x2);
                pa[mt][2] = f2tf32(odd ? y1 : y0);
                pa[mt][3] = f2tf32(odd ? y3 : y2);
            }
            #pragma unroll
            for (int ntd = 0; ntd < 8; ntd++) {
                uint2 bv = *(const uint2*)&Vs[(ntd * 8 + gid) * VS_STRIDE + (kk >> 1) * 16 + (kk & 1) * 8 + 2 * tig];
                uint32_t bf[2] = {bv.x, bv.y};
                mma_tf32(oac[0][ntd], pa[0], bf);
                mma_tf32(oac[1][ntd], pa[1], bf);
            }
        }
        __syncthreads();
    }

    #pragma unroll
    for (int mt = 0; mt < 2; mt++) {
        const float inv0 = 1.f / lrow[mt][0];
        const float inv1 = 1.f / lrow[mt][1];
        const int grow = nB * LQ + q0 + warpM + mt * 16 + gid;
        #pragma unroll
        for (int ntd = 0; ntd < 8; ntd++) {
            const int col = h * HD + ntd * 8 + 2 * tig;
            *(float2*)&g_attn[(size_t)grow * D + col] =
                make_float2(oac[mt][ntd][0] * inv0, oac[mt][ntd][1] * inv0);
            *(float2*)&g_attn[(size_t)(grow + 8) * D + col] =
                make_float2(oac[mt][ntd][2] * inv1, oac[mt][ntd][3] * inv1);
        }
    }
}

// ---------------------------------------------------------------------------
// Residual add + LayerNorm
// ---------------------------------------------------------------------------
__global__ __launch_bounds__(256)
void add_ln_kernel(const float* __restrict__ aext, int aid,
                   const float* __restrict__ bext, int bid,
                   const float* __restrict__ gamma,
                   const float* __restrict__ beta,
                   float* __restrict__ outext, int outid)
{
    const float* a = aext ? aext : scratch(aid);
    const float* b = bext ? bext : scratch(bid);
    float*       o = outext ? outext : scratch(outid);

    const int row = blockIdx.x;
    const int tid = threadIdx.x;
    const size_t base = (size_t)row * D;

    float v[4];
    float s = 0.f, s2 = 0.f;
    #pragma unroll
    for (int i = 0; i < 4; i++) {
        int col = tid + i * 256;
        float x = a[base + col] + b[base + col];
        v[i] = x;
        s  += x;
        s2 += x * x;
    }
    #pragma unroll
    for (int off = 16; off; off >>= 1) {
        s  += __shfl_xor_sync(0xFFFFFFFFu, s,  off);
        s2 += __shfl_xor_sync(0xFFFFFFFFu, s2, off);
    }
    __shared__ float rs[8], rs2[8];
    const int warp = tid >> 5, lane = tid & 31;
    if (lane == 0) { rs[warp] = s; rs2[warp] = s2; }
    __syncthreads();
    float ts = 0.f, ts2 = 0.f;
    #pragma unroll
    for (int w = 0; w < 8; w++) { ts += rs[w]; ts2 += rs2[w]; }

    const float mu  = ts * (1.f / D);
    const float var = ts2 * (1.f / D) - mu * mu;
    const float inv = rsqrtf(var + EPS);

    #pragma unroll
    for (int i = 0; i < 4; i++) {
        int col = tid + i * 256;
        o[base + col] = (v[i] - mu) * inv * gamma[col] + beta[col];
    }
}

// ---------------------------------------------------------------------------
// Launch
// ---------------------------------------------------------------------------
extern "C" void kernel_launch(void* const* d_in, const int* in_sizes, int n_in,
                              void* d_out, int out_size)
{
    const float* x     = (const float*)d_in[0];
    const float* w_qkv = (const float*)d_in[1];
    const float* b_qkv = (const float*)d_in[2];
    const float* w_o   = (const float*)d_in[3];
    const float* b_o   = (const float*)d_in[4];
    const float* g1    = (const float*)d_in[5];
    const float* be1   = (const float*)d_in[6];
    const float* w1    = (const float*)d_in[7];
    const float* b1    = (const float*)d_in[8];
    const float* w2    = (const float*)d_in[9];
    const float* b2    = (const float*)d_in[10];
    const float* g2    = (const float*)d_in[11];
    const float* be2   = (const float*)d_in[12];
    float* out = (float*)d_out;

    // Transpose weights -> [N,K] K-major operands
    transpose_k<<<dim3(3 * D / 32, D / 32), 256>>>(w_qkv, 6, D, 3 * D);
    transpose_k<<<dim3(D / 32,     D / 32), 256>>>(w_o,   7, D, D);
    transpose_k<<<dim3(FF / 32,    D / 32), 256>>>(w1,    8, D, FF);
    transpose_k<<<dim3(D / 32,    FF / 32), 256>>>(w2,    9, FF, D);

    // 1. QKV
    gemm_f16<<<dim3(3 * D / 128, MROWS / 128), 256>>>(
        x, -1, 6, b_qkv, nullptr, 0, MROWS, 3 * D, D, 0);

    // 2. attention (tensor-core flash)
    attn_mma<<<dim3(LQ / 128, H_, NB), 128>>>();

    // 3. proj
    gemm_f16<<<dim3(D / 128, MROWS / 128), 256>>>(
        nullptr, 1, 7, b_o, nullptr, 2, MROWS, D, D, 0);

    // 4. h = LN(proj + x)
    add_ln_kernel<<<MROWS, 256>>>(nullptr, 2, x, -1, g1, be1, nullptr, 3);

    // 5. FF1 (+ReLU)
    gemm_f16<<<dim3(FF / 128, MROWS / 128), 256>>>(
        nullptr, 3, 8, b1, nullptr, 4, MROWS, FF, D, 1);

    // 6. FF2
    gemm_f16<<<dim3(D / 128, MROWS / 128), 256>>>(
        nullptr, 4, 9, b2, nullptr, 5, MROWS, D, FF, 0);

    // 7. out = LN(h + ff2)
    add_ln_kernel<<<MROWS, 256>>>(nullptr, 3, nullptr, 5, g2, be2, out, -1);
}

// round 9
// speedup vs baseline: 1.9961x; 1.6351x over previous
#include <cuda_runtime.h>
#include <cuda_fp16.h>
#include <math.h>
#include <stdint.h>

// Problem constants
#define D     1024
#define H_    16
#define HD    64
#define FF    4096
#define NB    2
#define LQ    2048
#define MROWS (NB * LQ)   // 4096
#define EPS   1e-5f

// ---------------------------------------------------------------------------
// Scratch (device globals — no allocation allowed)
// ---------------------------------------------------------------------------
__device__ float g_qkv [MROWS * 3 * D];   // fp32 id 0
__device__ float g_proj[MROWS * D];       // fp32 id 1
__device__ float g_h   [MROWS * D];       // fp32 id 2
__device__ float g_ff2 [MROWS * D];       // fp32 id 3

__device__ __half g_x16   [MROWS * D];    // h id 0
__device__ __half g_attn16[MROWS * D];    // h id 1
__device__ __half g_h16   [MROWS * D];    // h id 2
__device__ __half g_ff116 [MROWS * FF];   // h id 3
__device__ __half g_wqkvT16[3 * D * D];   // h id 4
__device__ __half g_woT16 [D * D];        // h id 5
__device__ __half g_w1T16 [FF * D];       // h id 6
__device__ __half g_w2T16 [D * FF];       // h id 7

__device__ __forceinline__ float* scratch(int id) {
    switch (id) {
        case 0:  return g_qkv;
        case 1:  return g_proj;
        case 2:  return g_h;
        default: return g_ff2;
    }
}
__device__ __forceinline__ __half* scratch_h(int id) {
    switch (id) {
        case 0:  return g_x16;
        case 1:  return g_attn16;
        case 2:  return g_h16;
        case 3:  return g_ff116;
        case 4:  return g_wqkvT16;
        case 5:  return g_woT16;
        case 6:  return g_w1T16;
        default: return g_w2T16;
    }
}

// ---------------------------------------------------------------------------
// mma / async helpers (base sm_103 target OK)
// ---------------------------------------------------------------------------
__device__ __forceinline__ uint32_t f2tf32(float x) {
    uint32_t r;
    asm("cvt.rna.tf32.f32 %0, %1;" : "=r"(r) : "f"(x));
    return r;
}

__device__ __forceinline__ void mma_tf32(float* c, const uint32_t* a, const uint32_t* b) {
    asm volatile(
        "mma.sync.aligned.m16n8k8.row.col.f32.tf32.tf32.f32 "
        "{%0,%1,%2,%3}, {%4,%5,%6,%7}, {%8,%9}, {%0,%1,%2,%3};"
        : "+f"(c[0]), "+f"(c[1]), "+f"(c[2]), "+f"(c[3])
        : "r"(a[0]), "r"(a[1]), "r"(a[2]), "r"(a[3]),
          "r"(b[0]), "r"(b[1]));
}

__device__ __forceinline__ void mma_f16(float* c, const uint32_t* a, const uint32_t* b) {
    asm volatile(
        "mma.sync.aligned.m16n8k16.row.col.f32.f16.f16.f32 "
        "{%0,%1,%2,%3}, {%4,%5,%6,%7}, {%8,%9}, {%0,%1,%2,%3};"
        : "+f"(c[0]), "+f"(c[1]), "+f"(c[2]), "+f"(c[3])
        : "r"(a[0]), "r"(a[1]), "r"(a[2]), "r"(a[3]),
          "r"(b[0]), "r"(b[1]));
}

__device__ __forceinline__ uint32_t packh2(float a, float b) {
    __half2 h = __floats2half2_rn(a, b);
    return *(uint32_t*)&h;
}

__device__ __forceinline__ void cp_async16(uint32_t dst, const void* src) {
    asm volatile("cp.async.cg.shared.global [%0], [%1], 16;" :: "r"(dst), "l"(src));
}
__device__ __forceinline__ void cp_commit() {
    asm volatile("cp.async.commit_group;" ::: "memory");
}
__device__ __forceinline__ void cp_wait2() {
    asm volatile("cp.async.wait_group 2;" ::: "memory");
}

#define LDSM4(r0, r1, r2, r3, addr) \
    asm volatile("ldmatrix.sync.aligned.m8n8.x4.shared.b16 {%0,%1,%2,%3}, [%4];" \
                 : "=r"(r0), "=r"(r1), "=r"(r2), "=r"(r3) : "r"(addr))

// 64B-row XOR swizzle: 16B segment index for (row, chunk c in 0..3)
__device__ __forceinline__ int phys16(int row, int c) {
    return (row >> 1) * 8 + ((((row & 1) << 2) | c) ^ ((row >> 1) & 3));
}

// ---------------------------------------------------------------------------
// fp32 -> fp16 convert (x)
// ---------------------------------------------------------------------------
__global__ __launch_bounds__(256)
void cvt16_k(const float* __restrict__ src, int dstId)
{
    uint32_t* d = (uint32_t*)scratch_h(dstId);
    const int i = blockIdx.x * 256 + threadIdx.x;
    const float4 v = ((const float4*)src)[i];
    d[i * 2 + 0] = packh2(v.x, v.y);
    d[i * 2 + 1] = packh2(v.z, v.w);
}

// ---------------------------------------------------------------------------
// Weight transpose -> fp16: dst[c][r] = half(src[r][c])
// ---------------------------------------------------------------------------
__global__ __launch_bounds__(256)
void transpose_k(const float* __restrict__ src, int dstId, int R, int C)
{
    __shared__ float t[32][33];
    __half* dst = scratch_h(dstId);
    const int bx = blockIdx.x * 32;
    const int by = blockIdx.y * 32;
    const int tx = threadIdx.x & 31;
    const int ty = threadIdx.x >> 5;
    #pragma unroll
    for (int i = 0; i < 32; i += 8)
        t[ty + i][tx] = src[(size_t)(by + ty + i) * C + bx + tx];
    __syncthreads();
    #pragma unroll
    for (int i = 0; i < 32; i += 8)
        dst[(size_t)(bx + ty + i) * R + by + tx] = __float2half(t[tx][ty + i]);
}

// ---------------------------------------------------------------------------
// FP16 GEMM: C[M,N] = A[M,K] @ Bt[N,K]^T + bias (opt ReLU, opt fp16 out)
// A, Bt fp16 in global. Block 128x128, 8 warps (64x32), BK=32.
// 4-stage cp.async pipeline + ldmatrix.x4 frags on 64B-row XOR swizzle.
// ---------------------------------------------------------------------------
#define STAGE_B 16384
#define GEMM_SMEM (4 * STAGE_B)   // 65536

__global__ __launch_bounds__(256)
void gemm_f16(int Aid, int Bid, const float* __restrict__ bias,
              int Cid, int outHalf, int M, int N, int K, int relu)
{
    extern __shared__ char smem[];
    const uint32_t smem_u = (uint32_t)__cvta_generic_to_shared(smem);

    const __half* A  = scratch_h(Aid);
    const __half* Bt = scratch_h(Bid);

    const int tid  = threadIdx.x;
    const int wid  = tid >> 5;
    const int lane = tid & 31;
    const int gid  = lane >> 2;
    const int tig  = lane & 3;
    const int warpM = (wid & 1) * 64;
    const int warpN = (wid >> 1) * 32;
    const int m0 = blockIdx.y * 128;
    const int n0 = blockIdx.x * 128;

    // ---- loader precompute: 4 x 16B cp.async per thread per chunk ----
    uint32_t ld_dst[4];
    const __half* ld_src[4];
    #pragma unroll
    for (int j = 0; j < 4; j++) {
        const int s   = j * 256 + tid;       // 0..1023
        const int isB = s >= 512;
        const int ss  = s & 511;
        const int row = ss >> 2;
        const int c   = ss & 3;
        ld_dst[j] = (isB ? 8192u : 0u) + (uint32_t)phys16(row, c) * 16u;
        ld_src[j] = (isB ? Bt + (size_t)(n0 + row) * K
                         : A  + (size_t)(m0 + row) * K) + c * 8;
    }

    // ---- fragment ldmatrix address precompute (byte offsets in stage) ----
    const int hi = lane >> 4;                       // chunk parity
    const int rr = (lane & 7) + ((lane >> 3) & 1) * 8;
    uint32_t a_off[2][4], b_off[2][2];
    {
        const int ra = warpM + rr;
        const int la = ra >> 1, xa = (ra & 1) << 2, sa = la & 3;
        const int rb = warpN + rr;
        const int lb = rb >> 1, xb = (rb & 1) << 2, sb = lb & 3;
        #pragma unroll
        for (int ks = 0; ks < 2; ks++) {
            const int c = 2 * ks + hi;
            #pragma unroll
            for (int mt = 0; mt < 4; mt++)
                a_off[ks][mt] = (uint32_t)(la * 8 + mt * 64 + ((xa | c) ^ sa)) * 16u;
            #pragma unroll
            for (int n2 = 0; n2 < 2; n2++)
                b_off[ks][n2] = 8192u + (uint32_t)(lb * 8 + n2 * 64 + ((xb | c) ^ sb)) * 16u;
        }
    }

    float acc[4][4][4];
    #pragma unroll
    for (int mt = 0; mt < 4; mt++)
        #pragma unroll
        for (int nt = 0; nt < 4; nt++)
            #pragma unroll
            for (int c = 0; c < 4; c++) acc[mt][nt][c] = 0.f;

    const int nk = K >> 5;

    // ---- prolog: stages 0..2 ----
    for (int s = 0; s < 3; s++) {
        const uint32_t sb_ = smem_u + s * STAGE_B;
        #pragma unroll
        for (int j = 0; j < 4; j++)
            cp_async16(sb_ + ld_dst[j], ld_src[j] + s * 32);
        cp_commit();
    }

    for (int kc = 0; kc < nk; kc++) {
        cp_wait2();
        __syncthreads();

        if (kc + 3 < nk) {
            const uint32_t sb_ = smem_u + ((kc + 3) & 3) * STAGE_B;
            #pragma unroll
            for (int j = 0; j < 4; j++)
                cp_async16(sb_ + ld_dst[j], ld_src[j] + (kc + 3) * 32);
        }
        cp_commit();   // empty group at tail keeps wait_group accounting valid

        const uint32_t st = smem_u + (kc & 3) * STAGE_B;
        #pragma unroll
        for (int ks = 0; ks < 2; ks++) {
            uint32_t bfr[4][2];
            {
                uint32_t r0, r1, r2, r3;
                LDSM4(r0, r1, r2, r3, st + b_off[ks][0]);
                bfr[0][0] = r0; bfr[1][0] = r1; bfr[0][1] = r2; bfr[1][1] = r3;
            }
            {
                uint32_t r0, r1, r2, r3;
                LDSM4(r0, r1, r2, r3, st + b_off[ks][1]);
                bfr[2][0] = r0; bfr[3][0] = r1; bfr[2][1] = r2; bfr[3][1] = r3;
            }
            #pragma unroll
            for (int mt = 0; mt < 4; mt++) {
                uint32_t af[4];
                LDSM4(af[0], af[1], af[2], af[3], st + a_off[ks][mt]);
                #pragma unroll
                for (int nt = 0; nt < 4; nt++)
                    mma_f16(acc[mt][nt], af, bfr[nt]);
            }
        }
    }

    // ---- epilogue ----
    if (outHalf) {
        __half* C = scratch_h(Cid);
        #pragma unroll
        for (int nt = 0; nt < 4; nt++) {
            const int n = n0 + warpN + nt * 8 + 2 * tig;
            const float b0 = bias[n], b1 = bias[n + 1];
            #pragma unroll
            for (int mt = 0; mt < 4; mt++) {
                const int m = m0 + warpM + mt * 16 + gid;
                float v0 = acc[mt][nt][0] + b0, v1 = acc[mt][nt][1] + b1;
                float v2 = acc[mt][nt][2] + b0, v3 = acc[mt][nt][3] + b1;
                if (relu) {
                    v0 = fmaxf(v0, 0.f); v1 = fmaxf(v1, 0.f);
                    v2 = fmaxf(v2, 0.f); v3 = fmaxf(v3, 0.f);
                }
                *(uint32_t*)&C[(size_t)m * N + n]       = packh2(v0, v1);
                *(uint32_t*)&C[(size_t)(m + 8) * N + n] = packh2(v2, v3);
            }
        }
    } else {
        float* C = scratch(Cid);
        #pragma unroll
        for (int nt = 0; nt < 4; nt++) {
            const int n = n0 + warpN + nt * 8 + 2 * tig;
            const float b0 = bias[n], b1 = bias[n + 1];
            #pragma unroll
            for (int mt = 0; mt < 4; mt++) {
                const int m = m0 + warpM + mt * 16 + gid;
                float2 v0 = make_float2(acc[mt][nt][0] + b0, acc[mt][nt][1] + b1);
                float2 v1 = make_float2(acc[mt][nt][2] + b0, acc[mt][nt][3] + b1);
                if (relu) {
                    v0.x = fmaxf(v0.x, 0.f); v0.y = fmaxf(v0.y, 0.f);
                    v1.x = fmaxf(v1.x, 0.f); v1.y = fmaxf(v1.y, 0.f);
                }
                *(float2*)&C[(size_t)m * N + n]       = v0;
                *(float2*)&C[(size_t)(m + 8) * N + n] = v1;
            }
        }
    }
}

// ---------------------------------------------------------------------------
// Tensor-core flash attention (tf32 mma.sync), output -> fp16 g_attn16
// ---------------------------------------------------------------------------
#define KS_STRIDE 72
#define VS_STRIDE 74

__global__ __launch_bounds__(128)
void attn_mma()
{
    __shared__ uint32_t sm[64 * KS_STRIDE + 64 * VS_STRIDE];

    const int nB  = blockIdx.z;
    const int h   = blockIdx.y;
    const int q0  = blockIdx.x * 128;
    const int tid = threadIdx.x;
    const int wid = tid >> 5;
    const int lane = tid & 31;
    const int gid  = lane >> 2;
    const int tig  = lane & 3;
    const int warpM = wid * 32;
    const float qscale = 0.125f * 1.44269504f;

    #pragma unroll
    for (int t = 0; t < 16; t++) {
        const int i  = tid + t * 128;
        const int r  = i >> 4;
        const int c4 = i & 15;
        const float4 v = *(const float4*)&g_qkv[(size_t)(nB * LQ + q0 + r) * (3 * D) + h * HD + c4 * 4];
        uint32_t* dst = &sm[r * KS_STRIDE + (c4 >> 2) * 16 + ((c4 & 3) >> 1) * 8 + (c4 & 1)];
        dst[0] = f2tf32(v.x * qscale); dst[2] = f2tf32(v.y * qscale);
        dst[4] = f2tf32(v.z * qscale); dst[6] = f2tf32(v.w * qscale);
    }
    __syncthreads();

    uint32_t qf[2][8][4];
    #pragma unroll
    for (int mt = 0; mt < 2; mt++) {
        const int rlo = warpM + mt * 16 + gid;
        #pragma unroll
        for (int ks = 0; ks < 8; ks++) {
            uint2 lo = *(const uint2*)&sm[ rlo      * KS_STRIDE + (ks >> 1) * 16 + (ks & 1) * 8 + 2 * tig];
            uint2 hi = *(const uint2*)&sm[(rlo + 8) * KS_STRIDE + (ks >> 1) * 16 + (ks & 1) * 8 + 2 * tig];
            qf[mt][ks][0] = lo.x; qf[mt][ks][1] = hi.x;
            qf[mt][ks][2] = lo.y; qf[mt][ks][3] = hi.y;
        }
    }
    __syncthreads();

    uint32_t* Ks = sm;
    uint32_t* Vs = sm + 64 * KS_STRIDE;

    float oac[2][8][4];
    #pragma unroll
    for (int mt = 0; mt < 2; mt++)
        #pragma unroll
        for (int nt = 0; nt < 8; nt++)
            #pragma unroll
            for (int c = 0; c < 4; c++) oac[mt][nt][c] = 0.f;
    float mrow[2][2] = {{-1e30f, -1e30f}, {-1e30f, -1e30f}};
    float lrow[2][2] = {{0.f, 0.f}, {0.f, 0.f}};

    for (int kt = 0; kt < LQ / 64; kt++) {
        #pragma unroll
        for (int t = 0; t < 8; t++) {
            const int i  = tid + t * 128;
            const int r  = i >> 4;
            const int c4 = i & 15;
            const size_t base = (size_t)(nB * LQ + kt * 64 + r) * (3 * D) + h * HD + c4 * 4;
            const float4 v = *(const float4*)&g_qkv[base + D];
            uint32_t* dst = &Ks[r * KS_STRIDE + (c4 >> 2) * 16 + ((c4 & 3) >> 1) * 8 + (c4 & 1)];
            dst[0] = f2tf32(v.x); dst[2] = f2tf32(v.y);
            dst[4] = f2tf32(v.z); dst[6] = f2tf32(v.w);
        }
        #pragma unroll
        for (int t = 0; t < 8; t++) {
            const int i   = tid + t * 128;
            const int key = i >> 4;
            const int c4  = i & 15;
            const size_t base = (size_t)(nB * LQ + kt * 64 + key) * (3 * D) + h * HD + c4 * 4;
            const float4 v = *(const float4*)&g_qkv[base + 2 * D];
            const int kpos = (key >> 4) * 16 + ((key & 3) << 1) + ((key >> 2) & 1) + (key & 8);
            const int d0 = c4 * 4;
            Vs[(d0 + 0) * VS_STRIDE + kpos] = f2tf32(v.x);
            Vs[(d0 + 1) * VS_STRIDE + kpos] = f2tf32(v.y);
            Vs[(d0 + 2) * VS_STRIDE + kpos] = f2tf32(v.z);
            Vs[(d0 + 3) * VS_STRIDE + kpos] = f2tf32(v.w);
        }
        __syncthreads();

        float sacc[2][8][4];
        #pragma unroll
        for (int mt = 0; mt < 2; mt++)
            #pragma unroll
            for (int nt = 0; nt < 8; nt++)
                #pragma unroll
                for (int c = 0; c < 4; c++) sacc[mt][nt][c] = 0.f;

        #pragma unroll
        for (int ks = 0; ks < 8; ks++) {
            #pragma unroll
            for (int nt = 0; nt < 8; nt++) {
                uint2 bv = *(const uint2*)&Ks[(nt * 8 + gid) * KS_STRIDE + (ks >> 1) * 16 + (ks & 1) * 8 + 2 * tig];
                uint32_t bf[2] = {bv.x, bv.y};
                mma_tf32(sacc[0][nt], qf[0][ks], bf);
                mma_tf32(sacc[1][nt], qf[1][ks], bf);
            }
        }

        #pragma unroll
        for (int mt = 0; mt < 2; mt++) {
            float mx0 = -1e30f, mx1 = -1e30f;
            #pragma unroll
            for (int nt = 0; nt < 8; nt++) {
                mx0 = fmaxf(mx0, fmaxf(sacc[mt][nt][0], sacc[mt][nt][1]));
                mx1 = fmaxf(mx1, fmaxf(sacc[mt][nt][2], sacc[mt][nt][3]));
            }
            mx0 = fmaxf(mx0, __shfl_xor_sync(0xFFFFFFFFu, mx0, 1));
            mx0 = fmaxf(mx0, __shfl_xor_sync(0xFFFFFFFFu, mx0, 2));
            mx1 = fmaxf(mx1, __shfl_xor_sync(0xFFFFFFFFu, mx1, 1));
            mx1 = fmaxf(mx1, __shfl_xor_sync(0xFFFFFFFFu, mx1, 2));

            const float mn0 = fmaxf(mrow[mt][0], mx0);
            const float mn1 = fmaxf(mrow[mt][1], mx1);
            const float cr0 = exp2f(mrow[mt][0] - mn0);
            const float cr1 = exp2f(mrow[mt][1] - mn1);
            mrow[mt][0] = mn0;
            mrow[mt][1] = mn1;

            float ls0 = 0.f, ls1 = 0.f;
            #pragma unroll
            for (int nt = 0; nt < 8; nt++) {
                sacc[mt][nt][0] = exp2f(sacc[mt][nt][0] - mn0);
                sacc[mt][nt][1] = exp2f(sacc[mt][nt][1] - mn0);
                sacc[mt][nt][2] = exp2f(sacc[mt][nt][2] - mn1);
                sacc[mt][nt][3] = exp2f(sacc[mt][nt][3] - mn1);
                ls0 += sacc[mt][nt][0] + sacc[mt][nt][1];
                ls1 += sacc[mt][nt][2] + sacc[mt][nt][3];
            }
            ls0 += __shfl_xor_sync(0xFFFFFFFFu, ls0, 1);
            ls0 += __shfl_xor_sync(0xFFFFFFFFu, ls0, 2);
            ls1 += __shfl_xor_sync(0xFFFFFFFFu, ls1, 1);
            ls1 += __shfl_xor_sync(0xFFFFFFFFu, ls1, 2);
            lrow[mt][0] = lrow[mt][0] * cr0 + ls0;
            lrow[mt][1] = lrow[mt][1] * cr1 + ls1;

            #pragma unroll
            for (int nt = 0; nt < 8; nt++) {
                oac[mt][nt][0] *= cr0; oac[mt][nt][1] *= cr0;
                oac[mt][nt][2] *= cr1; oac[mt][nt][3] *= cr1;
            }
        }

        const int s1 = (lane & ~3) | (tig >> 1);
        const int s2 = s1 + 2;
        const bool odd = (tig & 1) != 0;
        #pragma unroll
        for (int kk = 0; kk < 8; kk++) {
            uint32_t pa[2][4];
            #pragma unroll
            for (int mt = 0; mt < 2; mt++) {
                const float c0 = sacc[mt][kk][0], c1 = sacc[mt][kk][1];
                const float c2 = sacc[mt][kk][2], c3 = sacc[mt][kk][3];
                const float x0 = __shfl_sync(0xFFFFFFFFu, c0, s1);
                const float x1 = __shfl_sync(0xFFFFFFFFu, c1, s1);
                const float x2 = __shfl_sync(0xFFFFFFFFu, c2, s1);
                const float x3 = __shfl_sync(0xFFFFFFFFu, c3, s1);
                const float y0 = __shfl_sync(0xFFFFFFFFu, c0, s2);
                const float y1 = __shfl_sync(0xFFFFFFFFu, c1, s2);
                const float y2 = __shfl_sync(0xFFFFFFFFu, c2, s2);
                const float y3 = __shfl_sync(0xFFFFFFFFu, c3, s2);
                pa[mt][0] = f2tf32(odd ? x1 : x0);
                pa[mt][1] = f2tf32(odd ? x3 : x2);
                pa[mt][2] = f2tf32(odd ? y1 : y0);
                pa[mt][3] = f2tf32(odd ? y3 : y2);
            }
            #pragma unroll
            for (int ntd = 0; ntd < 8; ntd++) {
                uint2 bv = *(const uint2*)&Vs[(ntd * 8 + gid) * VS_STRIDE + (kk >> 1) * 16 + (kk & 1) * 8 + 2 * tig];
                uint32_t bf[2] = {bv.x, bv.y};
                mma_tf32(oac[0][ntd], pa[0], bf);
                mma_tf32(oac[1][ntd], pa[1], bf);
            }
        }
        __syncthreads();
    }

    // normalize + store fp16 (consumed only by proj GEMM)
    #pragma unroll
    for (int mt = 0; mt < 2; mt++) {
        const float inv0 = 1.f / lrow[mt][0];
        const float inv1 = 1.f / lrow[mt][1];
        const int grow = nB * LQ + q0 + warpM + mt * 16 + gid;
        #pragma unroll
        for (int ntd = 0; ntd < 8; ntd++) {
            const int col = h * HD + ntd * 8 + 2 * tig;
            *(uint32_t*)&g_attn16[(size_t)grow * D + col] =
                packh2(oac[mt][ntd][0] * inv0, oac[mt][ntd][1] * inv0);
            *(uint32_t*)&g_attn16[(size_t)(grow + 8) * D + col] =
                packh2(oac[mt][ntd][2] * inv1, oac[mt][ntd][3] * inv1);
        }
    }
}

// ---------------------------------------------------------------------------
// Residual add + LayerNorm (optional fp16 shadow copy of output)
// ---------------------------------------------------------------------------
__global__ __launch_bounds__(256)
void add_ln_kernel(const float* __restrict__ aext, int aid,
                   const float* __restrict__ bext, int bid,
                   const float* __restrict__ gamma,
                   const float* __restrict__ beta,
                   float* __restrict__ outext, int outid, int hOutId)
{
    const float* a = aext ? aext : scratch(aid);
    const float* b = bext ? bext : scratch(bid);
    float*       o = outext ? outext : scratch(outid);

    const int row = blockIdx.x;
    const int tid = threadIdx.x;
    const size_t base = (size_t)row * D;

    float v[4];
    float s = 0.f, s2 = 0.f;
    #pragma unroll
    for (int i = 0; i < 4; i++) {
        int col = tid + i * 256;
        float x = a[base + col] + b[base + col];
        v[i] = x;
        s  += x;
        s2 += x * x;
    }
    #pragma unroll
    for (int off = 16; off; off >>= 1) {
        s  += __shfl_xor_sync(0xFFFFFFFFu, s,  off);
        s2 += __shfl_xor_sync(0xFFFFFFFFu, s2, off);
    }
    __shared__ float rs[8], rs2[8];
    const int warp = tid >> 5, lane = tid & 31;
    if (lane == 0) { rs[warp] = s; rs2[warp] = s2; }
    __syncthreads();
    float ts = 0.f, ts2 = 0.f;
    #pragma unroll
    for (int w = 0; w < 8; w++) { ts += rs[w]; ts2 += rs2[w]; }

    const float mu  = ts * (1.f / D);
    const float var = ts2 * (1.f / D) - mu * mu;
    const float inv = rsqrtf(var + EPS);

    __half* ho = (hOutId >= 0) ? scratch_h(hOutId) : (__half*)0;
    #pragma unroll
    for (int i = 0; i < 4; i++) {
        int col = tid + i * 256;
        float r = (v[i] - mu) * inv * gamma[col] + beta[col];
        o[base + col] = r;
        if (ho) ho[base + col] = __float2half(r);
    }
}

// ---------------------------------------------------------------------------
// Launch
// ---------------------------------------------------------------------------
extern "C" void kernel_launch(void* const* d_in, const int* in_sizes, int n_in,
                              void* d_out, int out_size)
{
    const float* x     = (const float*)d_in[0];
    const float* w_qkv = (const float*)d_in[1];
    const float* b_qkv = (const float*)d_in[2];
    const float* w_o   = (const float*)d_in[3];
    const float* b_o   = (const float*)d_in[4];
    const float* g1    = (const float*)d_in[5];
    const float* be1   = (const float*)d_in[6];
    const float* w1    = (const float*)d_in[7];
    const float* b1    = (const float*)d_in[8];
    const float* w2    = (const float*)d_in[9];
    const float* b2    = (const float*)d_in[10];
    const float* g2    = (const float*)d_in[11];
    const float* be2   = (const float*)d_in[12];
    float* out = (float*)d_out;

    cudaFuncSetAttribute(gemm_f16,
                         cudaFuncAttributeMaxDynamicSharedMemorySize, GEMM_SMEM);

    // operand prep: x -> fp16, weights -> transposed fp16
    cvt16_k<<<MROWS * D / 1024, 256>>>(x, 0);
    transpose_k<<<dim3(3 * D / 32, D / 32), 256>>>(w_qkv, 4, D, 3 * D);
    transpose_k<<<dim3(D / 32,     D / 32), 256>>>(w_o,   5, D, D);
    transpose_k<<<dim3(FF / 32,    D / 32), 256>>>(w1,    6, D, FF);
    transpose_k<<<dim3(D / 32,    FF / 32), 256>>>(w2,    9 - 2, FF, D);  // id 7

    // 1. QKV: x16 @ wqkvT16 -> g_qkv (fp32)
    gemm_f16<<<dim3(3 * D / 128, MROWS / 128), 256, GEMM_SMEM>>>(
        0, 4, b_qkv, 0, 0, MROWS, 3 * D, D, 0);

    // 2. attention -> g_attn16
    attn_mma<<<dim3(LQ / 128, H_, NB), 128>>>();

    // 3. proj: attn16 @ woT16 -> g_proj (fp32)
    gemm_f16<<<dim3(D / 128, MROWS / 128), 256, GEMM_SMEM>>>(
        1, 5, b_o, 1, 0, MROWS, D, D, 0);

    // 4. h = LN(proj + x) -> g_h (fp32) + g_h16
    add_ln_kernel<<<MROWS, 256>>>(nullptr, 1, x, -1, g1, be1, nullptr, 2, 2);

    // 5. FF1: h16 @ w1T16 + ReLU -> g_ff116 (fp16)
    gemm_f16<<<dim3(FF / 128, MROWS / 128), 256, GEMM_SMEM>>>(
        2, 6, b1, 3, 1, MROWS, FF, D, 1);

    // 6. FF2: ff116 @ w2T16 -> g_ff2 (fp32)
    gemm_f16<<<dim3(D / 128, MROWS / 128), 256, GEMM_SMEM>>>(
        3, 7, b2, 3, 0, MROWS, D, FF, 0);

    // 7. out = LN(h + ff2)
    add_ln_kernel<<<MROWS, 256>>>(nullptr, 2, nullptr, 3, g2, be2, out, -1, -1);
}

// round 10
// speedup vs baseline: 2.5872x; 1.2962x over previous
#include <cuda_runtime.h>
#include <cuda_fp16.h>
#include <math.h>
#include <stdint.h>

// Problem constants
#define D     1024
#define H_    16
#define HD    64
#define FF    4096
#define NB    2
#define LQ    2048
#define MROWS (NB * LQ)   // 4096
#define EPS   1e-5f

// ---------------------------------------------------------------------------
// Scratch (device globals — no allocation allowed)
// ---------------------------------------------------------------------------
__device__ float g_proj[MROWS * D];       // fp32 id 0
__device__ float g_h   [MROWS * D];       // fp32 id 1
__device__ float g_ff2 [MROWS * D];       // fp32 id 2

__device__ __half g_x16   [MROWS * D];    // h id 0
__device__ __half g_attn16[MROWS * D];    // h id 1
__device__ __half g_h16   [MROWS * D];    // h id 2
__device__ __half g_ff116 [MROWS * FF];   // h id 3
__device__ __half g_wqkvT16[3 * D * D];   // h id 4
__device__ __half g_woT16 [D * D];        // h id 5
__device__ __half g_w1T16 [FF * D];       // h id 6
__device__ __half g_w2T16 [D * FF];       // h id 7
__device__ __half g_qkv16 [MROWS * 3 * D];// h id 8

__device__ __forceinline__ float* scratch(int id) {
    switch (id) {
        case 0:  return g_proj;
        case 1:  return g_h;
        default: return g_ff2;
    }
}
__device__ __forceinline__ __half* scratch_h(int id) {
    switch (id) {
        case 0:  return g_x16;
        case 1:  return g_attn16;
        case 2:  return g_h16;
        case 3:  return g_ff116;
        case 4:  return g_wqkvT16;
        case 5:  return g_woT16;
        case 6:  return g_w1T16;
        case 7:  return g_w2T16;
        default: return g_qkv16;
    }
}

// ---------------------------------------------------------------------------
// mma / async helpers (base sm_103 target OK)
// ---------------------------------------------------------------------------
__device__ __forceinline__ void mma_f16(float* c, const uint32_t* a, const uint32_t* b) {
    asm volatile(
        "mma.sync.aligned.m16n8k16.row.col.f32.f16.f16.f32 "
        "{%0,%1,%2,%3}, {%4,%5,%6,%7}, {%8,%9}, {%0,%1,%2,%3};"
        : "+f"(c[0]), "+f"(c[1]), "+f"(c[2]), "+f"(c[3])
        : "r"(a[0]), "r"(a[1]), "r"(a[2]), "r"(a[3]),
          "r"(b[0]), "r"(b[1]));
}

__device__ __forceinline__ uint32_t packh2(float a, float b) {
    __half2 h = __floats2half2_rn(a, b);
    return *(uint32_t*)&h;
}

__device__ __forceinline__ void cp_async16(uint32_t dst, const void* src) {
    asm volatile("cp.async.cg.shared.global [%0], [%1], 16;" :: "r"(dst), "l"(src));
}
__device__ __forceinline__ void cp_commit() {
    asm volatile("cp.async.commit_group;" ::: "memory");
}
__device__ __forceinline__ void cp_wait2() {
    asm volatile("cp.async.wait_group 2;" ::: "memory");
}

#define LDSM4(r0, r1, r2, r3, addr) \
    asm volatile("ldmatrix.sync.aligned.m8n8.x4.shared.b16 {%0,%1,%2,%3}, [%4];" \
                 : "=r"(r0), "=r"(r1), "=r"(r2), "=r"(r3) : "r"(addr))

#define LDSM4T(r0, r1, r2, r3, addr) \
    asm volatile("ldmatrix.sync.aligned.m8n8.x4.trans.shared.b16 {%0,%1,%2,%3}, [%4];" \
                 : "=r"(r0), "=r"(r1), "=r"(r2), "=r"(r3) : "r"(addr))

// 64B-row XOR swizzle (GEMM stages): 16B segment for (row, chunk c in 0..3)
__device__ __forceinline__ int phys16(int row, int c) {
    return (row >> 1) * 8 + ((((row & 1) << 2) | c) ^ ((row >> 1) & 3));
}
// 128B-row XOR swizzle (attention tiles): seg for (row, seg-col c in 0..7)
#define ATT_SEG(row, c) (((row) * 8) + ((c) ^ ((row) & 7)))

// ---------------------------------------------------------------------------
// fp32 -> fp16 convert (x)
// ---------------------------------------------------------------------------
__global__ __launch_bounds__(256)
void cvt16_k(const float* __restrict__ src, int dstId)
{
    uint32_t* d = (uint32_t*)scratch_h(dstId);
    const int i = blockIdx.x * 256 + threadIdx.x;
    const float4 v = ((const float4*)src)[i];
    d[i * 2 + 0] = packh2(v.x, v.y);
    d[i * 2 + 1] = packh2(v.z, v.w);
}

// ---------------------------------------------------------------------------
// Weight transpose -> fp16: dst[c][r] = half(src[r][c])
// ---------------------------------------------------------------------------
__global__ __launch_bounds__(256)
void transpose_k(const float* __restrict__ src, int dstId, int R, int C)
{
    __shared__ float t[32][33];
    __half* dst = scratch_h(dstId);
    const int bx = blockIdx.x * 32;
    const int by = blockIdx.y * 32;
    const int tx = threadIdx.x & 31;
    const int ty = threadIdx.x >> 5;
    #pragma unroll
    for (int i = 0; i < 32; i += 8)
        t[ty + i][tx] = src[(size_t)(by + ty + i) * C + bx + tx];
    __syncthreads();
    #pragma unroll
    for (int i = 0; i < 32; i += 8)
        dst[(size_t)(bx + ty + i) * R + by + tx] = __float2half(t[tx][ty + i]);
}

// ---------------------------------------------------------------------------
// FP16 GEMM (R9-validated): C = A @ Bt^T + bias, 4-stage cp.async + ldmatrix
// ---------------------------------------------------------------------------
#define STAGE_B 16384
#define GEMM_SMEM (4 * STAGE_B)   // 65536

__global__ __launch_bounds__(256)
void gemm_f16(int Aid, int Bid, const float* __restrict__ bias,
              int Cid, int outHalf, int M, int N, int K, int relu)
{
    extern __shared__ char smem[];
    const uint32_t smem_u = (uint32_t)__cvta_generic_to_shared(smem);

    const __half* A  = scratch_h(Aid);
    const __half* Bt = scratch_h(Bid);

    const int tid  = threadIdx.x;
    const int wid  = tid >> 5;
    const int lane = tid & 31;
    const int gid  = lane >> 2;
    const int tig  = lane & 3;
    const int warpM = (wid & 1) * 64;
    const int warpN = (wid >> 1) * 32;
    const int m0 = blockIdx.y * 128;
    const int n0 = blockIdx.x * 128;

    uint32_t ld_dst[4];
    const __half* ld_src[4];
    #pragma unroll
    for (int j = 0; j < 4; j++) {
        const int s   = j * 256 + tid;
        const int isB = s >= 512;
        const int ss  = s & 511;
        const int row = ss >> 2;
        const int c   = ss & 3;
        ld_dst[j] = (isB ? 8192u : 0u) + (uint32_t)phys16(row, c) * 16u;
        ld_src[j] = (isB ? Bt + (size_t)(n0 + row) * K
                         : A  + (size_t)(m0 + row) * K) + c * 8;
    }

    const int hi = lane >> 4;
    const int rr = (lane & 7) + ((lane >> 3) & 1) * 8;
    uint32_t a_off[2][4], b_off[2][2];
    {
        const int ra = warpM + rr;
        const int la = ra >> 1, xa = (ra & 1) << 2, sa = la & 3;
        const int rb = warpN + rr;
        const int lb = rb >> 1, xb = (rb & 1) << 2, sb = lb & 3;
        #pragma unroll
        for (int ks = 0; ks < 2; ks++) {
            const int c = 2 * ks + hi;
            #pragma unroll
            for (int mt = 0; mt < 4; mt++)
                a_off[ks][mt] = (uint32_t)(la * 8 + mt * 64 + ((xa | c) ^ sa)) * 16u;
            #pragma unroll
            for (int n2 = 0; n2 < 2; n2++)
                b_off[ks][n2] = 8192u + (uint32_t)(lb * 8 + n2 * 64 + ((xb | c) ^ sb)) * 16u;
        }
    }

    float acc[4][4][4];
    #pragma unroll
    for (int mt = 0; mt < 4; mt++)
        #pragma unroll
        for (int nt = 0; nt < 4; nt++)
            #pragma unroll
            for (int c = 0; c < 4; c++) acc[mt][nt][c] = 0.f;

    const int nk = K >> 5;

    for (int s = 0; s < 3; s++) {
        const uint32_t sb_ = smem_u + s * STAGE_B;
        #pragma unroll
        for (int j = 0; j < 4; j++)
            cp_async16(sb_ + ld_dst[j], ld_src[j] + s * 32);
        cp_commit();
    }

    for (int kc = 0; kc < nk; kc++) {
        cp_wait2();
        __syncthreads();

        if (kc + 3 < nk) {
            const uint32_t sb_ = smem_u + ((kc + 3) & 3) * STAGE_B;
            #pragma unroll
            for (int j = 0; j < 4; j++)
                cp_async16(sb_ + ld_dst[j], ld_src[j] + (kc + 3) * 32);
        }
        cp_commit();

        const uint32_t st = smem_u + (kc & 3) * STAGE_B;
        #pragma unroll
        for (int ks = 0; ks < 2; ks++) {
            uint32_t bfr[4][2];
            {
                uint32_t r0, r1, r2, r3;
                LDSM4(r0, r1, r2, r3, st + b_off[ks][0]);
                bfr[0][0] = r0; bfr[1][0] = r1; bfr[0][1] = r2; bfr[1][1] = r3;
            }
            {
                uint32_t r0, r1, r2, r3;
                LDSM4(r0, r1, r2, r3, st + b_off[ks][1]);
                bfr[2][0] = r0; bfr[3][0] = r1; bfr[2][1] = r2; bfr[3][1] = r3;
            }
            #pragma unroll
            for (int mt = 0; mt < 4; mt++) {
                uint32_t af[4];
                LDSM4(af[0], af[1], af[2], af[3], st + a_off[ks][mt]);
                #pragma unroll
                for (int nt = 0; nt < 4; nt++)
                    mma_f16(acc[mt][nt], af, bfr[nt]);
            }
        }
    }

    if (outHalf) {
        __half* C = scratch_h(Cid);
        #pragma unroll
        for (int nt = 0; nt < 4; nt++) {
            const int n = n0 + warpN + nt * 8 + 2 * tig;
            const float b0 = bias[n], b1 = bias[n + 1];
            #pragma unroll
            for (int mt = 0; mt < 4; mt++) {
                const int m = m0 + warpM + mt * 16 + gid;
                float v0 = acc[mt][nt][0] + b0, v1 = acc[mt][nt][1] + b1;
                float v2 = acc[mt][nt][2] + b0, v3 = acc[mt][nt][3] + b1;
                if (relu) {
                    v0 = fmaxf(v0, 0.f); v1 = fmaxf(v1, 0.f);
                    v2 = fmaxf(v2, 0.f); v3 = fmaxf(v3, 0.f);
                }
                *(uint32_t*)&C[(size_t)m * N + n]       = packh2(v0, v1);
                *(uint32_t*)&C[(size_t)(m + 8) * N + n] = packh2(v2, v3);
            }
        }
    } else {
        float* C = scratch(Cid);
        #pragma unroll
        for (int nt = 0; nt < 4; nt++) {
            const int n = n0 + warpN + nt * 8 + 2 * tig;
            const float b0 = bias[n], b1 = bias[n + 1];
            #pragma unroll
            for (int mt = 0; mt < 4; mt++) {
                const int m = m0 + warpM + mt * 16 + gid;
                float2 v0 = make_float2(acc[mt][nt][0] + b0, acc[mt][nt][1] + b1);
                float2 v1 = make_float2(acc[mt][nt][2] + b0, acc[mt][nt][3] + b1);
                if (relu) {
                    v0.x = fmaxf(v0.x, 0.f); v0.y = fmaxf(v0.y, 0.f);
                    v1.x = fmaxf(v1.x, 0.f); v1.y = fmaxf(v1.y, 0.f);
                }
                *(float2*)&C[(size_t)m * N + n]       = v0;
                *(float2*)&C[(size_t)(m + 8) * N + n] = v1;
            }
        }
    }
}

// ---------------------------------------------------------------------------
// FP16 flash attention (m16n8k16 + ldmatrix). 128 q rows/block, 4 warps.
// Q/K/V fp16 from g_qkv16. S accum frag layout == P A-frag layout: no shuffles.
// K B-frags: ldmatrix.x4 (rows=key). V B-frags: ldmatrix.x4.trans (rows=key).
// ---------------------------------------------------------------------------
__global__ __launch_bounds__(128)
void attn_f16()
{
    __shared__ __align__(16) uint8_t sm[16384];
    const uint32_t su = (uint32_t)__cvta_generic_to_shared(sm);

    const int nB  = blockIdx.z;
    const int h   = blockIdx.y;
    const int q0  = blockIdx.x * 128;
    const int tid = threadIdx.x;
    const int wid = tid >> 5;
    const int lane = tid & 31;
    const int gid  = lane >> 2;
    const int tig  = lane & 3;
    const int warpM = wid * 32;
    const int rr = (lane & 7) + ((lane >> 3) & 1) * 8;
    const int hi = lane >> 4;
    const float qscale = 0.125f * 1.44269504f;

    // ---- stage Q (128 x 64 fp16), extract A-frags, release smem ----
    #pragma unroll
    for (int t = 0; t < 8; t++) {
        const int i = t * 128 + tid;
        const int row = i >> 3, c = i & 7;
        const __half* src = g_qkv16 + (size_t)(nB * LQ + q0 + row) * (3 * D) + h * HD + c * 8;
        *(uint4*)(sm + ATT_SEG(row, c) * 16) = *(const uint4*)src;
    }
    __syncthreads();

    uint32_t qf[2][4][4];
    #pragma unroll
    for (int mt = 0; mt < 2; mt++)
        #pragma unroll
        for (int kc = 0; kc < 4; kc++) {
            const int row = warpM + mt * 16 + rr;
            LDSM4(qf[mt][kc][0], qf[mt][kc][1], qf[mt][kc][2], qf[mt][kc][3],
                  su + ATT_SEG(row, 2 * kc + hi) * 16);
        }
    __syncthreads();

    float oac[2][8][4];
    #pragma unroll
    for (int mt = 0; mt < 2; mt++)
        #pragma unroll
        for (int nt = 0; nt < 8; nt++)
            #pragma unroll
            for (int c = 0; c < 4; c++) oac[mt][nt][c] = 0.f;
    float mrow[2][2] = {{-1e30f, -1e30f}, {-1e30f, -1e30f}};
    float lrow[2][2] = {{0.f, 0.f}, {0.f, 0.f}};

    for (int kt = 0; kt < LQ / 64; kt++) {
        // load K (offset 0) and V (offset 8192), 64 x 64 fp16 each
        #pragma unroll
        for (int t = 0; t < 4; t++) {
            const int i = t * 128 + tid;
            const int row = i >> 3, c = i & 7;
            const __half* base = g_qkv16 + (size_t)(nB * LQ + kt * 64 + row) * (3 * D) + h * HD + c * 8;
            *(uint4*)(sm + ATT_SEG(row, c) * 16)        = *(const uint4*)(base + D);
            *(uint4*)(sm + 8192 + ATT_SEG(row, c) * 16) = *(const uint4*)(base + 2 * D);
        }
        __syncthreads();

        // ---- S = Q @ K^T ----
        float sacc[2][8][4];
        #pragma unroll
        for (int mt = 0; mt < 2; mt++)
            #pragma unroll
            for (int nt = 0; nt < 8; nt++)
                #pragma unroll
                for (int c = 0; c < 4; c++) sacc[mt][nt][c] = 0.f;

        #pragma unroll
        for (int ks = 0; ks < 4; ks++) {
            uint32_t bfr[8][2];
            #pragma unroll
            for (int np = 0; np < 4; np++) {
                uint32_t r0, r1, r2, r3;
                LDSM4(r0, r1, r2, r3, su + ATT_SEG(np * 16 + rr, 2 * ks + hi) * 16);
                bfr[2 * np][0] = r0; bfr[2 * np + 1][0] = r1;
                bfr[2 * np][1] = r2; bfr[2 * np + 1][1] = r3;
            }
            #pragma unroll
            for (int mt = 0; mt < 2; mt++)
                #pragma unroll
                for (int nt = 0; nt < 8; nt++)
                    mma_f16(sacc[mt][nt], qf[mt][ks], bfr[nt]);
        }

        // ---- scale + online softmax on fragments ----
        #pragma unroll
        for (int mt = 0; mt < 2; mt++) {
            #pragma unroll
            for (int nt = 0; nt < 8; nt++) {
                sacc[mt][nt][0] *= qscale; sacc[mt][nt][1] *= qscale;
                sacc[mt][nt][2] *= qscale; sacc[mt][nt][3] *= qscale;
            }
            float mx0 = -1e30f, mx1 = -1e30f;
            #pragma unroll
            for (int nt = 0; nt < 8; nt++) {
                mx0 = fmaxf(mx0, fmaxf(sacc[mt][nt][0], sacc[mt][nt][1]));
                mx1 = fmaxf(mx1, fmaxf(sacc[mt][nt][2], sacc[mt][nt][3]));
            }
            mx0 = fmaxf(mx0, __shfl_xor_sync(0xFFFFFFFFu, mx0, 1));
            mx0 = fmaxf(mx0, __shfl_xor_sync(0xFFFFFFFFu, mx0, 2));
            mx1 = fmaxf(mx1, __shfl_xor_sync(0xFFFFFFFFu, mx1, 1));
            mx1 = fmaxf(mx1, __shfl_xor_sync(0xFFFFFFFFu, mx1, 2));

            const float mn0 = fmaxf(mrow[mt][0], mx0);
            const float mn1 = fmaxf(mrow[mt][1], mx1);
            const float cr0 = exp2f(mrow[mt][0] - mn0);
            const float cr1 = exp2f(mrow[mt][1] - mn1);
            mrow[mt][0] = mn0;
            mrow[mt][1] = mn1;

            float ls0 = 0.f, ls1 = 0.f;
            #pragma unroll
            for (int nt = 0; nt < 8; nt++) {
                sacc[mt][nt][0] = exp2f(sacc[mt][nt][0] - mn0);
                sacc[mt][nt][1] = exp2f(sacc[mt][nt][1] - mn0);
                sacc[mt][nt][2] = exp2f(sacc[mt][nt][2] - mn1);
                sacc[mt][nt][3] = exp2f(sacc[mt][nt][3] - mn1);
                ls0 += sacc[mt][nt][0] + sacc[mt][nt][1];
                ls1 += sacc[mt][nt][2] + sacc[mt][nt][3];
            }
            ls0 += __shfl_xor_sync(0xFFFFFFFFu, ls0, 1);
            ls0 += __shfl_xor_sync(0xFFFFFFFFu, ls0, 2);
            ls1 += __shfl_xor_sync(0xFFFFFFFFu, ls1, 1);
            ls1 += __shfl_xor_sync(0xFFFFFFFFu, ls1, 2);
            lrow[mt][0] = lrow[mt][0] * cr0 + ls0;
            lrow[mt][1] = lrow[mt][1] * cr1 + ls1;

            #pragma unroll
            for (int nt = 0; nt < 8; nt++) {
                oac[mt][nt][0] *= cr0; oac[mt][nt][1] *= cr0;
                oac[mt][nt][2] *= cr1; oac[mt][nt][3] *= cr1;
            }
        }

        // ---- O += P @ V  (P A-frags = packed S accum; V via ldmatrix.trans) ----
        #pragma unroll
        for (int kc = 0; kc < 4; kc++) {
            uint32_t vb[8][2];
            #pragma unroll
            for (int dp = 0; dp < 4; dp++) {
                uint32_t r0, r1, r2, r3;
                LDSM4T(r0, r1, r2, r3, su + 8192 + ATT_SEG(kc * 16 + rr, 2 * dp + hi) * 16);
                vb[2 * dp][0] = r0; vb[2 * dp][1] = r1;
                vb[2 * dp + 1][0] = r2; vb[2 * dp + 1][1] = r3;
            }
            uint32_t pa[2][4];
            #pragma unroll
            for (int mt = 0; mt < 2; mt++) {
                pa[mt][0] = packh2(sacc[mt][2 * kc][0],     sacc[mt][2 * kc][1]);
                pa[mt][1] = packh2(sacc[mt][2 * kc][2],     sacc[mt][2 * kc][3]);
                pa[mt][2] = packh2(sacc[mt][2 * kc + 1][0], sacc[mt][2 * kc + 1][1]);
                pa[mt][3] = packh2(sacc[mt][2 * kc + 1][2], sacc[mt][2 * kc + 1][3]);
            }
            #pragma unroll
            for (int mt = 0; mt < 2; mt++)
                #pragma unroll
                for (int ntd = 0; ntd < 8; ntd++)
                    mma_f16(oac[mt][ntd], pa[mt], vb[ntd]);
        }
        __syncthreads();
    }

    // ---- normalize + store fp16 ----
    #pragma unroll
    for (int mt = 0; mt < 2; mt++) {
        const float inv0 = 1.f / lrow[mt][0];
        const float inv1 = 1.f / lrow[mt][1];
        const int grow = nB * LQ + q0 + warpM + mt * 16 + gid;
        #pragma unroll
        for (int ntd = 0; ntd < 8; ntd++) {
            const int col = h * HD + ntd * 8 + 2 * tig;
            *(uint32_t*)&g_attn16[(size_t)grow * D + col] =
                packh2(oac[mt][ntd][0] * inv0, oac[mt][ntd][1] * inv0);
            *(uint32_t*)&g_attn16[(size_t)(grow + 8) * D + col] =
                packh2(oac[mt][ntd][2] * inv1, oac[mt][ntd][3] * inv1);
        }
    }
}

// ---------------------------------------------------------------------------
// Residual add + LayerNorm (optional fp16 shadow)
// ---------------------------------------------------------------------------
__global__ __launch_bounds__(256)
void add_ln_kernel(const float* __restrict__ aext, int aid,
                   const float* __restrict__ bext, int bid,
                   const float* __restrict__ gamma,
                   const float* __restrict__ beta,
                   float* __restrict__ outext, int outid, int hOutId)
{
    const float* a = aext ? aext : scratch(aid);
    const float* b = bext ? bext : scratch(bid);
    float*       o = outext ? outext : scratch(outid);

    const int row = blockIdx.x;
    const int tid = threadIdx.x;
    const size_t base = (size_t)row * D;

    float v[4];
    float s = 0.f, s2 = 0.f;
    #pragma unroll
    for (int i = 0; i < 4; i++) {
        int col = tid + i * 256;
        float x = a[base + col] + b[base + col];
        v[i] = x;
        s  += x;
        s2 += x * x;
    }
    #pragma unroll
    for (int off = 16; off; off >>= 1) {
        s  += __shfl_xor_sync(0xFFFFFFFFu, s,  off);
        s2 += __shfl_xor_sync(0xFFFFFFFFu, s2, off);
    }
    __shared__ float rs[8], rs2[8];
    const int warp = tid >> 5, lane = tid & 31;
    if (lane == 0) { rs[warp] = s; rs2[warp] = s2; }
    __syncthreads();
    float ts = 0.f, ts2 = 0.f;
    #pragma unroll
    for (int w = 0; w < 8; w++) { ts += rs[w]; ts2 += rs2[w]; }

    const float mu  = ts * (1.f / D);
    const float var = ts2 * (1.f / D) - mu * mu;
    const float inv = rsqrtf(var + EPS);

    __half* ho = (hOutId >= 0) ? scratch_h(hOutId) : (__half*)0;
    #pragma unroll
    for (int i = 0; i < 4; i++) {
        int col = tid + i * 256;
        float r = (v[i] - mu) * inv * gamma[col] + beta[col];
        o[base + col] = r;
        if (ho) ho[base + col] = __float2half(r);
    }
}

// ---------------------------------------------------------------------------
// Launch
// ---------------------------------------------------------------------------
extern "C" void kernel_launch(void* const* d_in, const int* in_sizes, int n_in,
                              void* d_out, int out_size)
{
    const float* x     = (const float*)d_in[0];
    const float* w_qkv = (const float*)d_in[1];
    const float* b_qkv = (const float*)d_in[2];
    const float* w_o   = (const float*)d_in[3];
    const float* b_o   = (const float*)d_in[4];
    const float* g1    = (const float*)d_in[5];
    const float* be1   = (const float*)d_in[6];
    const float* w1    = (const float*)d_in[7];
    const float* b1    = (const float*)d_in[8];
    const float* w2    = (const float*)d_in[9];
    const float* b2    = (const float*)d_in[10];
    const float* g2    = (const float*)d_in[11];
    const float* be2   = (const float*)d_in[12];
    float* out = (float*)d_out;

    cudaFuncSetAttribute(gemm_f16,
                         cudaFuncAttributeMaxDynamicSharedMemorySize, GEMM_SMEM);

    // operand prep
    cvt16_k<<<MROWS * D / 1024, 256>>>(x, 0);
    transpose_k<<<dim3(3 * D / 32, D / 32), 256>>>(w_qkv, 4, D, 3 * D);
    transpose_k<<<dim3(D / 32,     D / 32), 256>>>(w_o,   5, D, D);
    transpose_k<<<dim3(FF / 32,    D / 32), 256>>>(w1,    6, D, FF);
    transpose_k<<<dim3(D / 32,    FF / 32), 256>>>(w2,    7, FF, D);

    // 1. QKV: x16 @ wqkvT16 -> g_qkv16 (fp16)
    gemm_f16<<<dim3(3 * D / 128, MROWS / 128), 256, GEMM_SMEM>>>(
        0, 4, b_qkv, 8, 1, MROWS, 3 * D, D, 0);

    // 2. attention (fp16 tensor-core flash) -> g_attn16
    attn_f16<<<dim3(LQ / 128, H_, NB), 128>>>();

    // 3. proj: attn16 @ woT16 -> g_proj (fp32)
    gemm_f16<<<dim3(D / 128, MROWS / 128), 256, GEMM_SMEM>>>(
        1, 5, b_o, 0, 0, MROWS, D, D, 0);

    // 4. h = LN(proj + x) -> g_h (fp32) + g_h16
    add_ln_kernel<<<MROWS, 256>>>(nullptr, 0, x, -1, g1, be1, nullptr, 1, 2);

    // 5. FF1: h16 @ w1T16 + ReLU -> g_ff116 (fp16)
    gemm_f16<<<dim3(FF / 128, MROWS / 128), 256, GEMM_SMEM>>>(
        2, 6, b1, 3, 1, MROWS, FF, D, 1);

    // 6. FF2: ff116 @ w2T16 -> g_ff2 (fp32)
    gemm_f16<<<dim3(D / 128, MROWS / 128), 256, GEMM_SMEM>>>(
        3, 7, b2, 2, 0, MROWS, D, FF, 0);

    // 7. out = LN(h + ff2)
    add_ln_kernel<<<MROWS, 256>>>(nullptr, 1, nullptr, 2, g2, be2, out, -1, -1);
}